// round 2
// baseline (speedup 1.0000x reference)
#include <cuda_runtime.h>
#include <math.h>

// Problem dims
#define BB 128
#define PP 196
#define EE 256
#define AA 256
#define DD 512
#define MME 512      // embedding dim
#define VV 10000
#define LL 26
#define TT 25
#define KXX 768      // M + E (x = [emb, ctx])

// -------------------- scratch (device globals, no runtime alloc) ---------
__device__ float g_att1[(size_t)BB * PP * AA];   // 25.7 MB
__device__ float g_h[BB * DD];
__device__ float g_c[BB * DD];
__device__ float g_x[BB * KXX];                  // [emb | gated ctx]
__device__ float g_att2p[4 * BB * AA];           // split-K partials of h@Wd.T
__device__ float g_gatep[4 * BB * AA];           // split-K partials of h@Wfb.T
__device__ float g_gates0[BB * 4 * DD];          // x@Wih.T
__device__ float g_gates1[BB * 4 * DD];          // h@Whh.T

// -------------------- 64x64x16 SGEMM core, 64 threads, 8x8 microtile -----
// Computes acc[8][8] += A[m0:m0+64, kBeg:kEnd] * W[n0:n0+64, kBeg:kEnd]^T
// A: row-major (lda = K stride), W: row-major (N x K, ldw = K stride).
// Requires blockDim.x == 64, M tiles fully in-range, K multiple of 16,
// lda/ldw/kBeg multiples of 4. N-range guarded.
__device__ __forceinline__ void gemm_core64(
    const float* __restrict__ Amat, int lda,
    const float* __restrict__ Wmat, int ldw,
    int m0, int n0, int N, int kBeg, int kEnd,
    float acc[8][8])
{
    __shared__ float As[16][68];
    __shared__ float Bs[16][68];
    const int tid = threadIdx.x;
    const int tm  = (tid >> 3) << 3;   // 0..56 step 8
    const int tn  = (tid & 7) << 3;    // 0..56 step 8
    const int lm  = tid >> 2;          // 0..15
    const int lk  = (tid & 3) << 2;    // 0,4,8,12

    for (int k0 = kBeg; k0 < kEnd; k0 += 16) {
        #pragma unroll
        for (int r = 0; r < 4; r++) {
            int m = lm + 16 * r;
            float4 v = *(const float4*)(Amat + (size_t)(m0 + m) * lda + k0 + lk);
            As[lk + 0][m] = v.x; As[lk + 1][m] = v.y;
            As[lk + 2][m] = v.z; As[lk + 3][m] = v.w;
        }
        #pragma unroll
        for (int r = 0; r < 4; r++) {
            int n = lm + 16 * r;
            float4 v = make_float4(0.f, 0.f, 0.f, 0.f);
            if (n0 + n < N)
                v = *(const float4*)(Wmat + (size_t)(n0 + n) * ldw + k0 + lk);
            Bs[lk + 0][n] = v.x; Bs[lk + 1][n] = v.y;
            Bs[lk + 2][n] = v.z; Bs[lk + 3][n] = v.w;
        }
        __syncthreads();
        #pragma unroll
        for (int kk = 0; kk < 16; kk++) {
            float a[8], b[8];
            *(float4*)(a)     = *(const float4*)&As[kk][tm];
            *(float4*)(a + 4) = *(const float4*)&As[kk][tm + 4];
            *(float4*)(b)     = *(const float4*)&Bs[kk][tn];
            *(float4*)(b + 4) = *(const float4*)&Bs[kk][tn + 4];
            #pragma unroll
            for (int i = 0; i < 8; i++)
                #pragma unroll
                for (int j = 0; j < 8; j++)
                    acc[i][j] = fmaf(a[i], b[j], acc[i][j]);
        }
        __syncthreads();
    }
}

#define ZERO_ACC(acc) \
    { _Pragma("unroll") for (int i = 0; i < 8; i++) \
      _Pragma("unroll") for (int j = 0; j < 8; j++) acc[i][j] = 0.f; }

// -------------------- setup: mean, h0, c0 --------------------------------
__global__ __launch_bounds__(256) void mean_h0c0_kernel(
    const float* __restrict__ enc,
    const float* __restrict__ Wh0, const float* __restrict__ bh0,
    const float* __restrict__ Wc0, const float* __restrict__ bc0)
{
    __shared__ float ms[EE];
    const int b = blockIdx.x, tid = threadIdx.x;
    float acc = 0.f;
    const float* eb = enc + (size_t)b * PP * EE + tid;
    #pragma unroll 4
    for (int p = 0; p < PP; p++) acc += eb[(size_t)p * EE];
    ms[tid] = acc * (1.0f / PP);
    __syncthreads();
    for (int j = tid; j < DD; j += 256) {
        float h = bh0[j], c = bc0[j];
        const float* wh = Wh0 + (size_t)j * EE;
        const float* wc = Wc0 + (size_t)j * EE;
        #pragma unroll 4
        for (int k = 0; k < EE; k++) { h = fmaf(ms[k], wh[k], h); c = fmaf(ms[k], wc[k], c); }
        g_h[b * DD + j] = h;
        g_c[b * DD + j] = c;
    }
}

// -------------------- setup: att1 = enc @ We^T + be ----------------------
__global__ __launch_bounds__(64) void att1_kernel(
    const float* __restrict__ enc,
    const float* __restrict__ We, const float* __restrict__ be)
{
    float acc[8][8]; ZERO_ACC(acc);
    const int m0 = blockIdx.x * 64, n0 = blockIdx.y * 64;
    gemm_core64(enc, EE, We, EE, m0, n0, AA, 0, EE, acc);
    const int tid = threadIdx.x;
    const int tm = (tid >> 3) << 3, tn = (tid & 7) << 3;
    #pragma unroll
    for (int i = 0; i < 8; i++) {
        const int m = m0 + tm + i;
        #pragma unroll
        for (int j = 0; j < 8; j++) {
            const int n = n0 + tn + j;
            g_att1[(size_t)m * AA + n] = acc[i][j] + be[n];
        }
    }
}

// -------------------- per-step: att2 / forget-gate GEMM (split-K) --------
__global__ __launch_bounds__(64) void att2gate_kernel(
    const float* __restrict__ Wd, const float* __restrict__ Wfb,
    const int* __restrict__ lengths, int t)
{
    const int m0 = blockIdx.x * 64;
    if (t >= lengths[m0] - 1) return;   // lengths sorted desc -> whole tile inactive
    const int n0 = blockIdx.y * 64;
    const int part = blockIdx.z >> 2, s = blockIdx.z & 3;
    const float* Wm = part ? Wfb : Wd;
    float* C = (part ? g_gatep : g_att2p) + s * (BB * AA);
    float acc[8][8]; ZERO_ACC(acc);
    gemm_core64(g_h, DD, Wm, DD, m0, n0, AA, s * 128, s * 128 + 128, acc);
    const int tid = threadIdx.x;
    const int tm = (tid >> 3) << 3, tn = (tid & 7) << 3;
    #pragma unroll
    for (int i = 0; i < 8; i++)
        #pragma unroll
        for (int j = 0; j < 8; j++)
            C[(size_t)(m0 + tm + i) * AA + n0 + tn + j] = acc[i][j];
}

// -------------------- per-step: attention (scores/softmax/ctx/x) ---------
__global__ __launch_bounds__(256) void attn_kernel(
    const float* __restrict__ enc,
    const float* __restrict__ bd, const float* __restrict__ bfb,
    const float* __restrict__ wf, const float* __restrict__ bfp,
    const int* __restrict__ lengths, const int* __restrict__ captions,
    const float* __restrict__ embW, float* __restrict__ out_alpha, int t)
{
    __shared__ float att2_s[AA];
    __shared__ float wf_s[AA];
    __shared__ float gate_s[EE];
    __shared__ float alpha_s[PP];
    __shared__ float red[8];
    const int b = blockIdx.x, tid = threadIdx.x;
    float* arow = out_alpha + ((size_t)b * TT + t) * PP;
    const bool active = t < lengths[b] - 1;
    if (!active) {
        if (tid < PP) arow[tid] = 0.f;
        return;
    }
    // att2 + gate (sum split-K partials + bias)
    {
        const int j = tid;
        float a2 = bd[j], gv = bfb[j];
        #pragma unroll
        for (int s = 0; s < 4; s++) {
            a2 += g_att2p[s * (BB * AA) + b * AA + j];
            gv += g_gatep[s * (BB * AA) + b * AA + j];
        }
        att2_s[j] = a2;
        gate_s[j] = 1.f / (1.f + expf(-gv));
        wf_s[j] = wf[j];
    }
    __syncthreads();
    const float bfv = bfp[0];
    const int warp = tid >> 5, lane = tid & 31;
    // scores[p] = sum_a relu(att1 + att2) * wf  (warp per p)
    for (int p = warp; p < PP; p += 8) {
        const float* ar = g_att1 + ((size_t)(b * PP + p)) * AA + lane * 8;
        float4 v0 = *(const float4*)ar;
        float4 v1 = *(const float4*)(ar + 4);
        const int a0 = lane * 8;
        float s = 0.f;
        s += fmaxf(v0.x + att2_s[a0 + 0], 0.f) * wf_s[a0 + 0];
        s += fmaxf(v0.y + att2_s[a0 + 1], 0.f) * wf_s[a0 + 1];
        s += fmaxf(v0.z + att2_s[a0 + 2], 0.f) * wf_s[a0 + 2];
        s += fmaxf(v0.w + att2_s[a0 + 3], 0.f) * wf_s[a0 + 3];
        s += fmaxf(v1.x + att2_s[a0 + 4], 0.f) * wf_s[a0 + 4];
        s += fmaxf(v1.y + att2_s[a0 + 5], 0.f) * wf_s[a0 + 5];
        s += fmaxf(v1.z + att2_s[a0 + 6], 0.f) * wf_s[a0 + 6];
        s += fmaxf(v1.w + att2_s[a0 + 7], 0.f) * wf_s[a0 + 7];
        #pragma unroll
        for (int off = 16; off; off >>= 1) s += __shfl_down_sync(0xffffffffu, s, off);
        if (lane == 0) alpha_s[p] = s + bfv;
    }
    __syncthreads();
    // softmax over P
    const float sc = (tid < PP) ? alpha_s[tid] : -3.4e38f;
    float m = sc;
    #pragma unroll
    for (int off = 16; off; off >>= 1) m = fmaxf(m, __shfl_down_sync(0xffffffffu, m, off));
    if (lane == 0) red[warp] = m;
    __syncthreads();
    if (tid == 0) {
        float mm = red[0];
        #pragma unroll
        for (int i = 1; i < 8; i++) mm = fmaxf(mm, red[i]);
        red[0] = mm;
    }
    __syncthreads();
    const float mx = red[0];
    __syncthreads();
    const float ev = (tid < PP) ? expf(sc - mx) : 0.f;
    float sum = ev;
    #pragma unroll
    for (int off = 16; off; off >>= 1) sum += __shfl_down_sync(0xffffffffu, sum, off);
    if (lane == 0) red[warp] = sum;
    __syncthreads();
    if (tid == 0) {
        float ss = 0.f;
        #pragma unroll
        for (int i = 0; i < 8; i++) ss += red[i];
        red[0] = 1.f / ss;
    }
    __syncthreads();
    const float inv = red[0];
    if (tid < PP) {
        const float al = ev * inv;
        alpha_s[tid] = al;
        arow[tid] = al;
    }
    __syncthreads();
    // ctx[e] = sum_p enc[b,p,e] * alpha[p], gated; write x = [emb | ctx]
    {
        const int e = tid;
        float acc = 0.f;
        const float* eb = enc + (size_t)b * PP * EE + e;
        #pragma unroll 4
        for (int p = 0; p < PP; p++) acc = fmaf(eb[(size_t)p * EE], alpha_s[p], acc);
        g_x[b * KXX + MME + e] = acc * gate_s[e];
        const int cap = captions[b * LL + t];
        const float* er = embW + (size_t)cap * MME;
        for (int j = tid; j < MME; j += 256) g_x[b * KXX + j] = er[j];
    }
}

// -------------------- per-step: LSTM gates GEMMs -------------------------
__global__ __launch_bounds__(64) void gates_kernel(
    const float* __restrict__ Wih, const float* __restrict__ Whh,
    const int* __restrict__ lengths, int t)
{
    const int m0 = blockIdx.x * 64;
    if (t >= lengths[m0] - 1) return;
    const int n0 = blockIdx.y * 64;
    float acc[8][8]; ZERO_ACC(acc);
    if (blockIdx.z == 0)
        gemm_core64(g_x, KXX, Wih, KXX, m0, n0, 4 * DD, 0, KXX, acc);
    else
        gemm_core64(g_h, DD, Whh, DD, m0, n0, 4 * DD, 0, DD, acc);
    float* C = blockIdx.z ? g_gates1 : g_gates0;
    const int tid = threadIdx.x;
    const int tm = (tid >> 3) << 3, tn = (tid & 7) << 3;
    #pragma unroll
    for (int i = 0; i < 8; i++)
        #pragma unroll
        for (int j = 0; j < 8; j++)
            C[(size_t)(m0 + tm + i) * (4 * DD) + n0 + tn + j] = acc[i][j];
}

// -------------------- per-step: LSTM pointwise ---------------------------
__global__ __launch_bounds__(512) void lstm_kernel(
    const float* __restrict__ bih, const float* __restrict__ bhh,
    const int* __restrict__ lengths, int t)
{
    const int b = blockIdx.x, d = threadIdx.x;
    if (t >= lengths[b] - 1) return;
    const float* q0 = g_gates0 + (size_t)b * (4 * DD);
    const float* q1 = g_gates1 + (size_t)b * (4 * DD);
    const float iv = q0[d]            + q1[d]            + bih[d]            + bhh[d];
    const float fv = q0[DD + d]       + q1[DD + d]       + bih[DD + d]       + bhh[DD + d];
    const float gv = q0[2 * DD + d]   + q1[2 * DD + d]   + bih[2 * DD + d]   + bhh[2 * DD + d];
    const float ov = q0[3 * DD + d]   + q1[3 * DD + d]   + bih[3 * DD + d]   + bhh[3 * DD + d];
    const float c  = g_c[b * DD + d];
    const float si = 1.f / (1.f + expf(-iv));
    const float sf = 1.f / (1.f + expf(-fv));
    const float so = 1.f / (1.f + expf(-ov));
    const float cn = sf * c + si * tanhf(gv);
    const float hn = so * tanhf(cn);
    g_c[b * DD + d] = cn;
    g_h[b * DD + d] = hn;
}

// -------------------- per-step: vocab projection -------------------------
__global__ __launch_bounds__(64, 16) void pred_kernel(
    const float* __restrict__ Wfc, const float* __restrict__ bfc,
    const int* __restrict__ lengths, float* __restrict__ out, int t)
{
    const int m0 = blockIdx.x * 64, n0 = blockIdx.y * 64;
    const int tid = threadIdx.x;
    if (t >= lengths[m0] - 1) {
        // whole 64-row tile inactive: write zeros
        for (int idx = tid; idx < 64 * 64; idx += 64) {
            const int i = idx >> 6, j = idx & 63;
            const int n = n0 + j;
            if (n < VV) out[((size_t)(m0 + i) * TT + t) * VV + n] = 0.f;
        }
        return;
    }
    float acc[8][8]; ZERO_ACC(acc);
    gemm_core64(g_h, DD, Wfc, DD, m0, n0, VV, 0, DD, acc);
    const int tm = (tid >> 3) << 3, tn = (tid & 7) << 3;
    #pragma unroll
    for (int i = 0; i < 8; i++) {
        const int b = m0 + tm + i;
        const bool act = t < lengths[b] - 1;
        #pragma unroll
        for (int j = 0; j < 8; j++) {
            const int n = n0 + tn + j;
            if (n < VV)
                out[((size_t)b * TT + t) * VV + n] = act ? (acc[i][j] + bfc[n]) : 0.f;
        }
    }
}

// -------------------- launch -------------------------------------------
extern "C" void kernel_launch(void* const* d_in, const int* in_sizes, int n_in,
                              void* d_out, int out_size) {
    const float* enc      = (const float*)d_in[0];
    const int*   captions = (const int*)  d_in[1];
    const int*   lengths  = (const int*)  d_in[2];
    const float* embW     = (const float*)d_in[3];
    const float* We       = (const float*)d_in[4];
    const float* be       = (const float*)d_in[5];
    const float* Wd       = (const float*)d_in[6];
    const float* bd       = (const float*)d_in[7];
    const float* wf       = (const float*)d_in[8];
    const float* bf       = (const float*)d_in[9];
    const float* Wih      = (const float*)d_in[10];
    const float* bih      = (const float*)d_in[11];
    const float* Whh      = (const float*)d_in[12];
    const float* bhh      = (const float*)d_in[13];
    const float* Wh0      = (const float*)d_in[14];
    const float* bh0      = (const float*)d_in[15];
    const float* Wc0      = (const float*)d_in[16];
    const float* bc0      = (const float*)d_in[17];
    const float* Wfb      = (const float*)d_in[18];
    const float* bfb      = (const float*)d_in[19];
    const float* Wfc      = (const float*)d_in[20];
    const float* bfc      = (const float*)d_in[21];

    float* out_pred  = (float*)d_out;
    float* out_alpha = out_pred + (size_t)BB * TT * VV;

    mean_h0c0_kernel<<<BB, 256>>>(enc, Wh0, bh0, Wc0, bc0);
    att1_kernel<<<dim3((BB * PP) / 64, AA / 64), 64>>>(enc, We, be);

    for (int t = 0; t < TT; t++) {
        att2gate_kernel<<<dim3(2, AA / 64, 8), 64>>>(Wd, Wfb, lengths, t);
        attn_kernel<<<BB, 256>>>(enc, bd, bfb, wf, bf, lengths, captions,
                                 embW, out_alpha, t);
        gates_kernel<<<dim3(2, (4 * DD) / 64, 2), 64>>>(Wih, Whh, lengths, t);
        lstm_kernel<<<BB, 512>>>(bih, bhh, lengths, t);
        pred_kernel<<<dim3(2, (VV + 63) / 64), 64>>>(Wfc, bfc, lengths, out_pred, t);
    }
}

// round 4
// speedup vs baseline: 2.2505x; 2.2505x over previous
#include <cuda_runtime.h>
#include <math.h>

// Problem dims
#define BB 128
#define PP 196
#define EE 256
#define AA 256
#define DD 512
#define MME 512
#define VV 10000
#define LL 26
#define TT 25
#define KXH 1280     // emb(512) | ctx(256) | h(512)
#define NG  2048     // 4*DD gates
#define NW_TILES 79  // ceil(10000/128)

// -------------------- scratch --------------------------------------------
__device__ float g_att1[(size_t)BB * PP * AA];       // 25.7 MB
__device__ float g_c[BB * DD];
__device__ float g_xh[BB * KXH];                     // [emb | gated ctx | h]
__device__ float g_W[(size_t)NG * KXH];              // [Wih | Whh] 10.5 MB
__device__ float g_Wdg[512 * 512];                   // [Wd ; Wfb]
__device__ float g_attp[4 * BB * 512];               // split-K partials (att2|gate)
__device__ float g_gatesp[4 * (size_t)BB * NG];      // split-K partials gates

// -------------------- 64(M)x128(N) SGEMM core, 256 threads, 4x8 micro ----
// acc += A[m0:m0+64, kBeg:kEnd] * W[n0:n0+64.., kBeg:kEnd]^T
// A row-major (lda), W row-major N x K (ldw). K span multiple of 16,
// kBeg/lda/ldw multiples of 4. M tiles fully in range; N guarded.
__device__ __forceinline__ void gemm64x128(
    const float* __restrict__ Amat, int lda,
    const float* __restrict__ Wmat, int ldw,
    int m0, int n0, int N, int kBeg, int kEnd,
    float acc[4][8])
{
    __shared__ float As[16][68];
    __shared__ float Bs[16][132];
    const int tid = threadIdx.x;
    const int ar  = tid >> 2;          // 0..63
    const int ak  = (tid & 3) << 2;    // 0,4,8,12
    const int tx  = tid & 15;          // col group
    const int ty  = tid >> 4;          // row group
    const bool okB0 = (n0 + ar)      < N;
    const bool okB1 = (n0 + ar + 64) < N;
    const float* Arow = Amat + (size_t)(m0 + ar) * lda + ak;
    const float* Wrow0 = Wmat + (size_t)(n0 + ar) * ldw + ak;
    const float* Wrow1 = Wmat + (size_t)(n0 + ar + 64) * ldw + ak;

    for (int k0 = kBeg; k0 < kEnd; k0 += 16) {
        float4 va = *(const float4*)(Arow + k0);
        float4 vb0 = okB0 ? *(const float4*)(Wrow0 + k0) : make_float4(0.f,0.f,0.f,0.f);
        float4 vb1 = okB1 ? *(const float4*)(Wrow1 + k0) : make_float4(0.f,0.f,0.f,0.f);
        As[ak+0][ar] = va.x;  As[ak+1][ar] = va.y;
        As[ak+2][ar] = va.z;  As[ak+3][ar] = va.w;
        Bs[ak+0][ar] = vb0.x; Bs[ak+1][ar] = vb0.y;
        Bs[ak+2][ar] = vb0.z; Bs[ak+3][ar] = vb0.w;
        Bs[ak+0][ar+64] = vb1.x; Bs[ak+1][ar+64] = vb1.y;
        Bs[ak+2][ar+64] = vb1.z; Bs[ak+3][ar+64] = vb1.w;
        __syncthreads();
        #pragma unroll
        for (int kk = 0; kk < 16; kk++) {
            float a[4], b[8];
            *(float4*)(a)     = *(const float4*)&As[kk][ty << 2];
            *(float4*)(b)     = *(const float4*)&Bs[kk][tx << 3];
            *(float4*)(b + 4) = *(const float4*)&Bs[kk][(tx << 3) + 4];
            #pragma unroll
            for (int i = 0; i < 4; i++)
                #pragma unroll
                for (int j = 0; j < 8; j++)
                    acc[i][j] = fmaf(a[i], b[j], acc[i][j]);
        }
        __syncthreads();
    }
}

#define ZERO_ACC4(acc) \
    { _Pragma("unroll") for (int i = 0; i < 4; i++) \
      _Pragma("unroll") for (int j = 0; j < 8; j++) acc[i][j] = 0.f; }

// -------------------- setup: concat weights ------------------------------
__global__ __launch_bounds__(256) void concat_kernel(
    const float* __restrict__ Wih, const float* __restrict__ Whh,
    const float* __restrict__ Wd,  const float* __restrict__ Wfb)
{
    const int idx = blockIdx.x * 256 + threadIdx.x;
    if (idx < NG * KXH) {
        const int r = idx / KXH, c = idx - r * KXH;
        g_W[idx] = (c < 768) ? Wih[r * 768 + c] : Whh[r * 512 + (c - 768)];
    }
    if (idx < 512 * 512) {
        const int r = idx >> 9, c = idx & 511;
        g_Wdg[idx] = (r < 256) ? Wd[r * 512 + c] : Wfb[(r - 256) * 512 + c];
    }
}

// -------------------- setup: mean, h0, c0 --------------------------------
__global__ __launch_bounds__(256) void mean_h0c0_kernel(
    const float* __restrict__ enc,
    const float* __restrict__ Wh0, const float* __restrict__ bh0,
    const float* __restrict__ Wc0, const float* __restrict__ bc0)
{
    __shared__ float ms[EE];
    const int b = blockIdx.x, tid = threadIdx.x;
    float acc = 0.f;
    const float* eb = enc + (size_t)b * PP * EE + tid;
    #pragma unroll 4
    for (int p = 0; p < PP; p++) acc += eb[(size_t)p * EE];
    ms[tid] = acc * (1.0f / PP);
    __syncthreads();
    for (int j = tid; j < DD; j += 256) {
        float h = bh0[j], c = bc0[j];
        const float* wh = Wh0 + (size_t)j * EE;
        const float* wc = Wc0 + (size_t)j * EE;
        #pragma unroll 4
        for (int k = 0; k < EE; k++) { h = fmaf(ms[k], wh[k], h); c = fmaf(ms[k], wc[k], c); }
        g_xh[b * KXH + 768 + j] = h;
        g_c[b * DD + j] = c;
    }
}

// -------------------- setup: att1 = enc @ We^T + be ----------------------
__global__ __launch_bounds__(256) void att1_kernel(
    const float* __restrict__ enc,
    const float* __restrict__ We, const float* __restrict__ be)
{
    float acc[4][8]; ZERO_ACC4(acc);
    const int m0 = blockIdx.x * 64, n0 = blockIdx.y * 128;
    gemm64x128(enc, EE, We, EE, m0, n0, AA, 0, EE, acc);
    const int tx = threadIdx.x & 15, ty = threadIdx.x >> 4;
    #pragma unroll
    for (int i = 0; i < 4; i++) {
        const int m = m0 + (ty << 2) + i;
        #pragma unroll
        for (int j = 0; j < 8; j++) {
            const int n = n0 + (tx << 3) + j;
            g_att1[(size_t)m * AA + n] = acc[i][j] + be[n];
        }
    }
}

// -------------------- per-step: att2|gate GEMM (split-K=4) ---------------
__global__ __launch_bounds__(256) void att2_kernel(
    const int* __restrict__ lengths, int t)
{
    const int m0 = blockIdx.x * 64;
    if (t >= lengths[m0] - 1) return;           // sorted desc
    const int n0 = blockIdx.y * 128;
    const int s = blockIdx.z;
    float acc[4][8]; ZERO_ACC4(acc);
    gemm64x128(g_xh + 768, KXH, g_Wdg, 512, m0, n0, 512,
               s * 128, s * 128 + 128, acc);
    float* C = g_attp + s * (BB * 512);
    const int tx = threadIdx.x & 15, ty = threadIdx.x >> 4;
    #pragma unroll
    for (int i = 0; i < 4; i++)
        #pragma unroll
        for (int j = 0; j < 8; j++)
            C[(size_t)(m0 + (ty << 2) + i) * 512 + n0 + (tx << 3) + j] = acc[i][j];
}

// -------------------- per-step: attention fused --------------------------
__global__ __launch_bounds__(512) void attn_kernel(
    const float* __restrict__ enc,
    const float* __restrict__ bd, const float* __restrict__ bfb,
    const float* __restrict__ wf, const float* __restrict__ bfp,
    const int* __restrict__ lengths, const int* __restrict__ captions,
    const float* __restrict__ embW, float* __restrict__ out_alpha, int t)
{
    __shared__ float att2_s[AA];
    __shared__ float wf_s[AA];
    __shared__ float gate_s[EE];
    __shared__ float alpha_s[256];
    __shared__ float red[16];
    __shared__ float ctxp[2][EE];
    const int b = blockIdx.x, tid = threadIdx.x;
    float* arow = out_alpha + ((size_t)b * TT + t) * PP;
    if (t >= lengths[b] - 1) {
        if (tid < PP) arow[tid] = 0.f;
        return;
    }
    // reduce split-K partials: cols 0..255 = att2, 256..511 = fb-gate
    if (tid < 256) {
        float a2 = bd[tid];
        #pragma unroll
        for (int s = 0; s < 4; s++) a2 += g_attp[s * (BB * 512) + b * 512 + tid];
        att2_s[tid] = a2;
        wf_s[tid] = wf[tid];
    } else {
        const int j = tid - 256;
        float gv = bfb[j];
        #pragma unroll
        for (int s = 0; s < 4; s++) gv += g_attp[s * (BB * 512) + b * 512 + 256 + j];
        gate_s[j] = 1.f / (1.f + expf(-gv));
    }
    __syncthreads();
    const float bfv = bfp[0];
    const int warp = tid >> 5, lane = tid & 31;
    // scores[p] (warp per p, 16 warps)
    for (int p = warp; p < PP; p += 16) {
        const float* ar = g_att1 + ((size_t)(b * PP + p)) * AA + lane * 8;
        float4 v0 = *(const float4*)ar;
        float4 v1 = *(const float4*)(ar + 4);
        const int a0 = lane * 8;
        float s = 0.f;
        s += fmaxf(v0.x + att2_s[a0 + 0], 0.f) * wf_s[a0 + 0];
        s += fmaxf(v0.y + att2_s[a0 + 1], 0.f) * wf_s[a0 + 1];
        s += fmaxf(v0.z + att2_s[a0 + 2], 0.f) * wf_s[a0 + 2];
        s += fmaxf(v0.w + att2_s[a0 + 3], 0.f) * wf_s[a0 + 3];
        s += fmaxf(v1.x + att2_s[a0 + 4], 0.f) * wf_s[a0 + 4];
        s += fmaxf(v1.y + att2_s[a0 + 5], 0.f) * wf_s[a0 + 5];
        s += fmaxf(v1.z + att2_s[a0 + 6], 0.f) * wf_s[a0 + 6];
        s += fmaxf(v1.w + att2_s[a0 + 7], 0.f) * wf_s[a0 + 7];
        #pragma unroll
        for (int off = 16; off; off >>= 1) s += __shfl_down_sync(0xffffffffu, s, off);
        if (lane == 0) alpha_s[p] = s + bfv;
    }
    __syncthreads();
    // softmax over 196
    const float sc = (tid < PP) ? alpha_s[tid] : -3.4e38f;
    float m = sc;
    #pragma unroll
    for (int off = 16; off; off >>= 1) m = fmaxf(m, __shfl_down_sync(0xffffffffu, m, off));
    if (lane == 0) red[warp] = m;
    __syncthreads();
    if (tid == 0) {
        float mm = red[0];
        #pragma unroll
        for (int i = 1; i < 16; i++) mm = fmaxf(mm, red[i]);
        red[0] = mm;
    }
    __syncthreads();
    const float mx = red[0];
    __syncthreads();
    const float ev = (tid < PP) ? expf(sc - mx) : 0.f;
    float sum = ev;
    #pragma unroll
    for (int off = 16; off; off >>= 1) sum += __shfl_down_sync(0xffffffffu, sum, off);
    if (lane == 0) red[warp] = sum;
    __syncthreads();
    if (tid == 0) {
        float ss = 0.f;
        #pragma unroll
        for (int i = 0; i < 16; i++) ss += red[i];
        red[0] = 1.f / ss;
    }
    __syncthreads();
    const float inv = red[0];
    if (tid < PP) {
        const float al = ev * inv;
        alpha_s[tid] = al;
        arow[tid] = al;
    }
    __syncthreads();
    // ctx[e] = sum_p enc[b,p,e] * alpha[p] (two half-P partials)
    {
        const int e = tid & 255, half = tid >> 8;
        const int pB = half * 98, pE = pB + 98;
        float acc = 0.f;
        const float* eb = enc + (size_t)b * PP * EE + e;
        #pragma unroll 4
        for (int p = pB; p < pE; p++) acc = fmaf(eb[(size_t)p * EE], alpha_s[p], acc);
        ctxp[half][e] = acc;
    }
    __syncthreads();
    if (tid < 256)
        g_xh[b * KXH + 512 + tid] = (ctxp[0][tid] + ctxp[1][tid]) * gate_s[tid];
    // emb
    {
        const int cap = captions[b * LL + t];
        g_xh[b * KXH + tid] = embW[(size_t)cap * MME + tid];
    }
}

// -------------------- per-step: fused gates GEMM (split-K=4) -------------
__global__ __launch_bounds__(256) void gates_kernel(
    const int* __restrict__ lengths, int t)
{
    const int m0 = blockIdx.x * 64;
    if (t >= lengths[m0] - 1) return;
    const int n0 = blockIdx.y * 128;
    const int s = blockIdx.z;
    float acc[4][8]; ZERO_ACC4(acc);
    gemm64x128(g_xh, KXH, g_W, KXH, m0, n0, NG, s * 320, s * 320 + 320, acc);
    float* C = g_gatesp + (size_t)s * (BB * NG);
    const int tx = threadIdx.x & 15, ty = threadIdx.x >> 4;
    #pragma unroll
    for (int i = 0; i < 4; i++)
        #pragma unroll
        for (int j = 0; j < 8; j++)
            C[(size_t)(m0 + (ty << 2) + i) * NG + n0 + (tx << 3) + j] = acc[i][j];
}

// -------------------- per-step: LSTM pointwise (reduce + act) ------------
__global__ __launch_bounds__(512) void lstm_kernel(
    const float* __restrict__ bih, const float* __restrict__ bhh,
    const int* __restrict__ lengths, int t)
{
    const int b = blockIdx.x, d = threadIdx.x;
    if (t >= lengths[b] - 1) return;
    float v[4];
    #pragma unroll
    for (int g = 0; g < 4; g++) {
        const int n = g * DD + d;
        float x = bih[n] + bhh[n];
        #pragma unroll
        for (int s = 0; s < 4; s++)
            x += g_gatesp[(size_t)s * (BB * NG) + (size_t)b * NG + n];
        v[g] = x;
    }
    const float c  = g_c[b * DD + d];
    const float si = 1.f / (1.f + expf(-v[0]));
    const float sf = 1.f / (1.f + expf(-v[1]));
    const float so = 1.f / (1.f + expf(-v[3]));
    const float cn = sf * c + si * tanhf(v[2]);
    const float hn = so * tanhf(cn);
    g_c[b * DD + d] = cn;
    g_xh[b * KXH + 768 + d] = hn;
}

// -------------------- per-step: vocab projection -------------------------
__global__ __launch_bounds__(256) void pred_kernel(
    const float* __restrict__ Wfc, const float* __restrict__ bfc,
    const int* __restrict__ lengths, float* __restrict__ out, int t)
{
    const int m0 = blockIdx.x * 64, n0 = blockIdx.y * 128;
    const int tid = threadIdx.x;
    if (t >= lengths[m0] - 1) {
        for (int idx = tid; idx < 64 * 128; idx += 256) {
            const int i = idx >> 7, j = idx & 127;
            const int n = n0 + j;
            if (n < VV) out[((size_t)(m0 + i) * TT + t) * VV + n] = 0.f;
        }
        return;
    }
    float acc[4][8]; ZERO_ACC4(acc);
    gemm64x128(g_xh + 768, KXH, Wfc, DD, m0, n0, VV, 0, DD, acc);
    const int tx = tid & 15, ty = tid >> 4;
    #pragma unroll
    for (int i = 0; i < 4; i++) {
        const int b = m0 + (ty << 2) + i;
        const bool act = t < lengths[b] - 1;
        #pragma unroll
        for (int j = 0; j < 8; j++) {
            const int n = n0 + (tx << 3) + j;
            if (n < VV)
                out[((size_t)b * TT + t) * VV + n] = act ? (acc[i][j] + bfc[n]) : 0.f;
        }
    }
}

// -------------------- launch -------------------------------------------
extern "C" void kernel_launch(void* const* d_in, const int* in_sizes, int n_in,
                              void* d_out, int out_size) {
    const float* enc      = (const float*)d_in[0];
    const int*   captions = (const int*)  d_in[1];
    const int*   lengths  = (const int*)  d_in[2];
    const float* embW     = (const float*)d_in[3];
    const float* We       = (const float*)d_in[4];
    const float* be       = (const float*)d_in[5];
    const float* Wd       = (const float*)d_in[6];
    const float* bd       = (const float*)d_in[7];
    const float* wf       = (const float*)d_in[8];
    const float* bf       = (const float*)d_in[9];
    const float* Wih      = (const float*)d_in[10];
    const float* bih      = (const float*)d_in[11];
    const float* Whh      = (const float*)d_in[12];
    const float* bhh      = (const float*)d_in[13];
    const float* Wh0      = (const float*)d_in[14];
    const float* bh0      = (const float*)d_in[15];
    const float* Wc0      = (const float*)d_in[16];
    const float* bc0      = (const float*)d_in[17];
    const float* Wfb      = (const float*)d_in[18];
    const float* bfb      = (const float*)d_in[19];
    const float* Wfc      = (const float*)d_in[20];
    const float* bfc      = (const float*)d_in[21];

    float* out_pred  = (float*)d_out;
    float* out_alpha = out_pred + (size_t)BB * TT * VV;

    concat_kernel<<<(NG * KXH + 255) / 256, 256>>>(Wih, Whh, Wd, Wfb);
    mean_h0c0_kernel<<<BB, 256>>>(enc, Wh0, bh0, Wc0, bc0);
    att1_kernel<<<dim3((BB * PP) / 64, AA / 128), 256>>>(enc, We, be);

    for (int t = 0; t < TT; t++) {
        att2_kernel<<<dim3(2, 4, 4), 256>>>(lengths, t);
        attn_kernel<<<BB, 512>>>(enc, bd, bfb, wf, bf, lengths, captions,
                                 embW, out_alpha, t);
        gates_kernel<<<dim3(2, NG / 128, 4), 256>>>(lengths, t);
        lstm_kernel<<<BB, 512>>>(bih, bhh, lengths, t);
        pred_kernel<<<dim3(2, NW_TILES), 256>>>(Wfc, bfc, lengths, out_pred, t);
    }
}

// round 5
// speedup vs baseline: 2.4422x; 1.0852x over previous
#include <cuda_runtime.h>
#include <math.h>

// Problem dims
#define BB 128
#define PP 196
#define EE 256
#define AA 256
#define DD 512
#define MME 512
#define VV 10000
#define LL 26
#define TT 25
#define KXH 1280     // emb(512) | ctx(256) | h(512)
#define NG  2048     // 4*DD gates
#define NW_TILES 79  // ceil(10000/128)
#define NS_ATT 16    // split-K for att2
#define NS_G   5     // split-K for gates

// -------------------- scratch --------------------------------------------
__device__ float g_att1[(size_t)BB * PP * AA];        // 25.7 MB
__device__ float g_c[BB * DD];
__device__ float g_xh[BB * KXH];                      // [emb | gated ctx | h]
__device__ float g_W[(size_t)NG * KXH];               // [Wih | Whh]
__device__ float g_Wdg[512 * 512];                    // [Wd ; Wfb]
__device__ float g_attp[NS_ATT * BB * 512];           // split-K partials (att2|gate)
__device__ float g_gatesp[NS_G * (size_t)BB * NG];    // split-K partials gates

// ---- 64(M)x128(N) SGEMM core, 256 threads, 4x8 micro, double-buffered ---
// acc += A[m0:m0+64, kBeg:kEnd] * W[n0:n0+128, kBeg:kEnd]^T
// A row-major (lda), W row-major N x K (ldw). K span multiple of 16 (>=32),
// kBeg/lda/ldw multiples of 4. M tiles fully in range; N guarded.
__device__ __forceinline__ void gemm64x128(
    const float* __restrict__ Amat, int lda,
    const float* __restrict__ Wmat, int ldw,
    int m0, int n0, int N, int kBeg, int kEnd,
    float acc[4][8])
{
    __shared__ float As[2][16][68];
    __shared__ float Bs[2][16][132];
    const int tid = threadIdx.x;
    const int ar  = tid >> 2;          // 0..63
    const int ak  = (tid & 3) << 2;    // 0,4,8,12
    const int tx  = tid & 15;
    const int ty  = tid >> 4;
    const bool okB0 = (n0 + ar)      < N;
    const bool okB1 = (n0 + ar + 64) < N;
    const float* Arow  = Amat + (size_t)(m0 + ar) * lda + ak;
    const float* Wrow0 = Wmat + (size_t)(n0 + ar) * ldw + ak;
    const float* Wrow1 = Wmat + (size_t)(n0 + ar + 64) * ldw + ak;
    const float4 f40 = make_float4(0.f, 0.f, 0.f, 0.f);

    // preload tile 0
    float4 va  = *(const float4*)(Arow + kBeg);
    float4 vb0 = okB0 ? *(const float4*)(Wrow0 + kBeg) : f40;
    float4 vb1 = okB1 ? *(const float4*)(Wrow1 + kBeg) : f40;
    int buf = 0;
    As[0][ak+0][ar] = va.x;  As[0][ak+1][ar] = va.y;
    As[0][ak+2][ar] = va.z;  As[0][ak+3][ar] = va.w;
    Bs[0][ak+0][ar] = vb0.x; Bs[0][ak+1][ar] = vb0.y;
    Bs[0][ak+2][ar] = vb0.z; Bs[0][ak+3][ar] = vb0.w;
    Bs[0][ak+0][ar+64] = vb1.x; Bs[0][ak+1][ar+64] = vb1.y;
    Bs[0][ak+2][ar+64] = vb1.z; Bs[0][ak+3][ar+64] = vb1.w;
    __syncthreads();

    for (int k0 = kBeg; k0 < kEnd; k0 += 16) {
        const bool more = (k0 + 16) < kEnd;
        float4 na = f40, nb0 = f40, nb1 = f40;
        if (more) {
            na  = *(const float4*)(Arow + k0 + 16);
            if (okB0) nb0 = *(const float4*)(Wrow0 + k0 + 16);
            if (okB1) nb1 = *(const float4*)(Wrow1 + k0 + 16);
        }
        #pragma unroll
        for (int kk = 0; kk < 16; kk++) {
            float a[4], b[8];
            *(float4*)(a)     = *(const float4*)&As[buf][kk][ty << 2];
            *(float4*)(b)     = *(const float4*)&Bs[buf][kk][tx << 3];
            *(float4*)(b + 4) = *(const float4*)&Bs[buf][kk][(tx << 3) + 4];
            #pragma unroll
            for (int i = 0; i < 4; i++)
                #pragma unroll
                for (int j = 0; j < 8; j++)
                    acc[i][j] = fmaf(a[i], b[j], acc[i][j]);
        }
        if (more) {
            buf ^= 1;
            As[buf][ak+0][ar] = na.x;  As[buf][ak+1][ar] = na.y;
            As[buf][ak+2][ar] = na.z;  As[buf][ak+3][ar] = na.w;
            Bs[buf][ak+0][ar] = nb0.x; Bs[buf][ak+1][ar] = nb0.y;
            Bs[buf][ak+2][ar] = nb0.z; Bs[buf][ak+3][ar] = nb0.w;
            Bs[buf][ak+0][ar+64] = nb1.x; Bs[buf][ak+1][ar+64] = nb1.y;
            Bs[buf][ak+2][ar+64] = nb1.z; Bs[buf][ak+3][ar+64] = nb1.w;
            __syncthreads();
        }
    }
}

#define ZERO_ACC4(acc) \
    { _Pragma("unroll") for (int i = 0; i < 4; i++) \
      _Pragma("unroll") for (int j = 0; j < 8; j++) acc[i][j] = 0.f; }

// -------------------- setup: concat weights ------------------------------
__global__ __launch_bounds__(256) void concat_kernel(
    const float* __restrict__ Wih, const float* __restrict__ Whh,
    const float* __restrict__ Wd,  const float* __restrict__ Wfb)
{
    const int idx = blockIdx.x * 256 + threadIdx.x;
    if (idx < NG * KXH) {
        const int r = idx / KXH, c = idx - r * KXH;
        g_W[idx] = (c < 768) ? Wih[r * 768 + c] : Whh[r * 512 + (c - 768)];
    }
    if (idx < 512 * 512) {
        const int r = idx >> 9, c = idx & 511;
        g_Wdg[idx] = (r < 256) ? Wd[r * 512 + c] : Wfb[(r - 256) * 512 + c];
    }
}

// -------------------- setup: mean, h0, c0 --------------------------------
__global__ __launch_bounds__(256) void mean_h0c0_kernel(
    const float* __restrict__ enc,
    const float* __restrict__ Wh0, const float* __restrict__ bh0,
    const float* __restrict__ Wc0, const float* __restrict__ bc0)
{
    __shared__ float ms[EE];
    const int b = blockIdx.x, tid = threadIdx.x;
    float acc = 0.f;
    const float* eb = enc + (size_t)b * PP * EE + tid;
    #pragma unroll 4
    for (int p = 0; p < PP; p++) acc += eb[(size_t)p * EE];
    ms[tid] = acc * (1.0f / PP);
    __syncthreads();
    for (int j = tid; j < DD; j += 256) {
        float h = bh0[j], c = bc0[j];
        const float* wh = Wh0 + (size_t)j * EE;
        const float* wc = Wc0 + (size_t)j * EE;
        #pragma unroll 4
        for (int k = 0; k < EE; k++) { h = fmaf(ms[k], wh[k], h); c = fmaf(ms[k], wc[k], c); }
        g_xh[b * KXH + 768 + j] = h;
        g_c[b * DD + j] = c;
    }
}

// -------------------- setup: att1 = enc @ We^T + be ----------------------
__global__ __launch_bounds__(256) void att1_kernel(
    const float* __restrict__ enc,
    const float* __restrict__ We, const float* __restrict__ be)
{
    float acc[4][8]; ZERO_ACC4(acc);
    const int m0 = blockIdx.x * 64, n0 = blockIdx.y * 128;
    gemm64x128(enc, EE, We, EE, m0, n0, AA, 0, EE, acc);
    const int tx = threadIdx.x & 15, ty = threadIdx.x >> 4;
    #pragma unroll
    for (int i = 0; i < 4; i++) {
        const int m = m0 + (ty << 2) + i;
        #pragma unroll
        for (int j = 0; j < 8; j++) {
            const int n = n0 + (tx << 3) + j;
            g_att1[(size_t)m * AA + n] = acc[i][j] + be[n];
        }
    }
}

// -------------------- per-step: att2|gate GEMM (split-K=16) --------------
__global__ __launch_bounds__(256) void att2_kernel(
    const int* __restrict__ lengths, int t)
{
    const int m0 = blockIdx.x * 64;
    if (t >= lengths[m0] - 1) return;           // sorted desc
    const int n0 = blockIdx.y * 128;
    const int s = blockIdx.z;
    float acc[4][8]; ZERO_ACC4(acc);
    gemm64x128(g_xh + 768, KXH, g_Wdg, 512, m0, n0, 512,
               s * 32, s * 32 + 32, acc);
    float* C = g_attp + s * (BB * 512);
    const int tx = threadIdx.x & 15, ty = threadIdx.x >> 4;
    #pragma unroll
    for (int i = 0; i < 4; i++)
        #pragma unroll
        for (int j = 0; j < 8; j++)
            C[(size_t)(m0 + (ty << 2) + i) * 512 + n0 + (tx << 3) + j] = acc[i][j];
}

// -------------------- per-step: attention fused --------------------------
__global__ __launch_bounds__(512) void attn_kernel(
    const float* __restrict__ enc,
    const float* __restrict__ bd, const float* __restrict__ bfb,
    const float* __restrict__ wf, const float* __restrict__ bfp,
    const int* __restrict__ lengths, const int* __restrict__ captions,
    const float* __restrict__ embW, float* __restrict__ out_alpha, int t)
{
    __shared__ float att2_s[AA];
    __shared__ float wf_s[AA];
    __shared__ float gate_s[EE];
    __shared__ float alpha_s[256];
    __shared__ float red[16];
    __shared__ float ctxp[2][EE];
    const int b = blockIdx.x, tid = threadIdx.x;
    float* arow = out_alpha + ((size_t)b * TT + t) * PP;
    if (t >= lengths[b] - 1) {
        if (tid < PP) arow[tid] = 0.f;
        return;
    }
    // reduce split-K partials: cols 0..255 = att2, 256..511 = fb-gate
    if (tid < 256) {
        float a2 = bd[tid];
        #pragma unroll
        for (int s = 0; s < NS_ATT; s++) a2 += g_attp[s * (BB * 512) + b * 512 + tid];
        att2_s[tid] = a2;
        wf_s[tid] = wf[tid];
    } else {
        const int j = tid - 256;
        float gv = bfb[j];
        #pragma unroll
        for (int s = 0; s < NS_ATT; s++) gv += g_attp[s * (BB * 512) + b * 512 + 256 + j];
        gate_s[j] = 1.f / (1.f + expf(-gv));
    }
    __syncthreads();
    const float bfv = bfp[0];
    const int warp = tid >> 5, lane = tid & 31;
    // scores[p] (warp per p, 16 warps), software-pipelined loads
    {
        const float* base = g_att1 + (size_t)b * PP * AA + lane * 8;
        int p = warp;
        float4 v0 = make_float4(0,0,0,0), v1 = make_float4(0,0,0,0);
        if (p < PP) {
            v0 = *(const float4*)(base + (size_t)p * AA);
            v1 = *(const float4*)(base + (size_t)p * AA + 4);
        }
        for (; p < PP; p += 16) {
            const int pn = p + 16;
            float4 n0v = make_float4(0,0,0,0), n1v = make_float4(0,0,0,0);
            if (pn < PP) {
                n0v = *(const float4*)(base + (size_t)pn * AA);
                n1v = *(const float4*)(base + (size_t)pn * AA + 4);
            }
            const int a0 = lane * 8;
            float s = 0.f;
            s += fmaxf(v0.x + att2_s[a0 + 0], 0.f) * wf_s[a0 + 0];
            s += fmaxf(v0.y + att2_s[a0 + 1], 0.f) * wf_s[a0 + 1];
            s += fmaxf(v0.z + att2_s[a0 + 2], 0.f) * wf_s[a0 + 2];
            s += fmaxf(v0.w + att2_s[a0 + 3], 0.f) * wf_s[a0 + 3];
            s += fmaxf(v1.x + att2_s[a0 + 4], 0.f) * wf_s[a0 + 4];
            s += fmaxf(v1.y + att2_s[a0 + 5], 0.f) * wf_s[a0 + 5];
            s += fmaxf(v1.z + att2_s[a0 + 6], 0.f) * wf_s[a0 + 6];
            s += fmaxf(v1.w + att2_s[a0 + 7], 0.f) * wf_s[a0 + 7];
            #pragma unroll
            for (int off = 16; off; off >>= 1) s += __shfl_down_sync(0xffffffffu, s, off);
            if (lane == 0) alpha_s[p] = s + bfv;
            v0 = n0v; v1 = n1v;
        }
    }
    __syncthreads();
    // softmax over 196
    const float sc = (tid < PP) ? alpha_s[tid] : -3.4e38f;
    float m = sc;
    #pragma unroll
    for (int off = 16; off; off >>= 1) m = fmaxf(m, __shfl_down_sync(0xffffffffu, m, off));
    if (lane == 0) red[warp] = m;
    __syncthreads();
    if (tid == 0) {
        float mm = red[0];
        #pragma unroll
        for (int i = 1; i < 16; i++) mm = fmaxf(mm, red[i]);
        red[0] = mm;
    }
    __syncthreads();
    const float mx = red[0];
    __syncthreads();
    const float ev = (tid < PP) ? expf(sc - mx) : 0.f;
    float sum = ev;
    #pragma unroll
    for (int off = 16; off; off >>= 1) sum += __shfl_down_sync(0xffffffffu, sum, off);
    if (lane == 0) red[warp] = sum;
    __syncthreads();
    if (tid == 0) {
        float ss = 0.f;
        #pragma unroll
        for (int i = 0; i < 16; i++) ss += red[i];
        red[0] = 1.f / ss;
    }
    __syncthreads();
    const float inv = red[0];
    if (tid < PP) {
        const float al = ev * inv;
        alpha_s[tid] = al;
        arow[tid] = al;
    }
    __syncthreads();
    // ctx[e] = sum_p enc[b,p,e] * alpha[p] (two half-P partials)
    {
        const int e = tid & 255, half = tid >> 8;
        const int pB = half * 98, pE = pB + 98;
        float acc = 0.f;
        const float* eb = enc + (size_t)b * PP * EE + e;
        #pragma unroll 8
        for (int p = pB; p < pE; p++) acc = fmaf(eb[(size_t)p * EE], alpha_s[p], acc);
        ctxp[half][e] = acc;
    }
    __syncthreads();
    if (tid < 256)
        g_xh[b * KXH + 512 + tid] = (ctxp[0][tid] + ctxp[1][tid]) * gate_s[tid];
    // emb
    {
        const int cap = captions[b * LL + t];
        g_xh[b * KXH + tid] = embW[(size_t)cap * MME + tid];
    }
}

// -------------------- per-step: fused gates GEMM (split-K=5) -------------
__global__ __launch_bounds__(256) void gates_kernel(
    const int* __restrict__ lengths, int t)
{
    const int m0 = blockIdx.x * 64;
    if (t >= lengths[m0] - 1) return;
    const int n0 = blockIdx.y * 128;
    const int s = blockIdx.z;
    float acc[4][8]; ZERO_ACC4(acc);
    gemm64x128(g_xh, KXH, g_W, KXH, m0, n0, NG, s * 256, s * 256 + 256, acc);
    float* C = g_gatesp + (size_t)s * (BB * NG);
    const int tx = threadIdx.x & 15, ty = threadIdx.x >> 4;
    #pragma unroll
    for (int i = 0; i < 4; i++)
        #pragma unroll
        for (int j = 0; j < 8; j++)
            C[(size_t)(m0 + (ty << 2) + i) * NG + n0 + (tx << 3) + j] = acc[i][j];
}

// -------------------- per-step: LSTM pointwise (reduce + act) ------------
__global__ __launch_bounds__(512) void lstm_kernel(
    const float* __restrict__ bih, const float* __restrict__ bhh,
    const int* __restrict__ lengths, int t)
{
    const int b = blockIdx.x, d = threadIdx.x;
    if (t >= lengths[b] - 1) return;
    float v[4];
    #pragma unroll
    for (int g = 0; g < 4; g++) {
        const int n = g * DD + d;
        float x = bih[n] + bhh[n];
        #pragma unroll
        for (int s = 0; s < NS_G; s++)
            x += g_gatesp[(size_t)s * (BB * NG) + (size_t)b * NG + n];
        v[g] = x;
    }
    const float c  = g_c[b * DD + d];
    const float si = 1.f / (1.f + expf(-v[0]));
    const float sf = 1.f / (1.f + expf(-v[1]));
    const float so = 1.f / (1.f + expf(-v[3]));
    const float cn = sf * c + si * tanhf(v[2]);
    const float hn = so * tanhf(cn);
    g_c[b * DD + d] = cn;
    g_xh[b * KXH + 768 + d] = hn;
}

// -------------------- per-step: vocab projection -------------------------
__global__ __launch_bounds__(256) void pred_kernel(
    const float* __restrict__ Wfc, const float* __restrict__ bfc,
    const int* __restrict__ lengths, float* __restrict__ out, int t)
{
    const int m0 = blockIdx.x * 64, n0 = blockIdx.y * 128;
    const int tid = threadIdx.x;
    if (t >= lengths[m0] - 1) {
        for (int idx = tid; idx < 64 * 128; idx += 256) {
            const int i = idx >> 7, j = idx & 127;
            const int n = n0 + j;
            if (n < VV) out[((size_t)(m0 + i) * TT + t) * VV + n] = 0.f;
        }
        return;
    }
    float acc[4][8]; ZERO_ACC4(acc);
    gemm64x128(g_xh + 768, KXH, Wfc, DD, m0, n0, VV, 0, DD, acc);
    const int tx = tid & 15, ty = tid >> 4;
    #pragma unroll
    for (int i = 0; i < 4; i++) {
        const int b = m0 + (ty << 2) + i;
        const bool act = t < lengths[b] - 1;
        #pragma unroll
        for (int j = 0; j < 8; j++) {
            const int n = n0 + (tx << 3) + j;
            if (n < VV)
                out[((size_t)b * TT + t) * VV + n] = act ? (acc[i][j] + bfc[n]) : 0.f;
        }
    }
}

// -------------------- launch -------------------------------------------
extern "C" void kernel_launch(void* const* d_in, const int* in_sizes, int n_in,
                              void* d_out, int out_size) {
    const float* enc      = (const float*)d_in[0];
    const int*   captions = (const int*)  d_in[1];
    const int*   lengths  = (const int*)  d_in[2];
    const float* embW     = (const float*)d_in[3];
    const float* We       = (const float*)d_in[4];
    const float* be       = (const float*)d_in[5];
    const float* Wd       = (const float*)d_in[6];
    const float* bd       = (const float*)d_in[7];
    const float* wf       = (const float*)d_in[8];
    const float* bf       = (const float*)d_in[9];
    const float* Wih      = (const float*)d_in[10];
    const float* bih      = (const float*)d_in[11];
    const float* Whh      = (const float*)d_in[12];
    const float* bhh      = (const float*)d_in[13];
    const float* Wh0      = (const float*)d_in[14];
    const float* bh0      = (const float*)d_in[15];
    const float* Wc0      = (const float*)d_in[16];
    const float* bc0      = (const float*)d_in[17];
    const float* Wfb      = (const float*)d_in[18];
    const float* bfb      = (const float*)d_in[19];
    const float* Wfc      = (const float*)d_in[20];
    const float* bfc      = (const float*)d_in[21];

    float* out_pred  = (float*)d_out;
    float* out_alpha = out_pred + (size_t)BB * TT * VV;

    concat_kernel<<<(NG * KXH + 255) / 256, 256>>>(Wih, Whh, Wd, Wfb);
    mean_h0c0_kernel<<<BB, 256>>>(enc, Wh0, bh0, Wc0, bc0);
    att1_kernel<<<dim3((BB * PP) / 64, AA / 128), 256>>>(enc, We, be);

    for (int t = 0; t < TT; t++) {
        att2_kernel<<<dim3(2, 4, NS_ATT), 256>>>(lengths, t);
        attn_kernel<<<BB, 512>>>(enc, bd, bfb, wf, bf, lengths, captions,
                                 embW, out_alpha, t);
        gates_kernel<<<dim3(2, NG / 128, NS_G), 256>>>(lengths, t);
        lstm_kernel<<<BB, 512>>>(bih, bhh, lengths, t);
        pred_kernel<<<dim3(2, NW_TILES), 256>>>(Wfc, bfc, lengths, out_pred, t);
    }
}

// round 6
// speedup vs baseline: 3.7921x; 1.5527x over previous
#include <cuda_runtime.h>
#include <math.h>
#include <stdint.h>

// Problem dims
#define BB 128
#define PP 196
#define EE 256
#define AA 256
#define DD 512
#define MME 512
#define VV 10000
#define LL 26
#define TT 25
#define KXH 1280     // emb(512) | ctx(256) | h(512)
#define NG  2048     // 4*DD gates
#define NS_ATT 16    // split-K for att2
#define NS_G   5     // split-K for gates
#define PRED_BN 64
#define PRED_GRID 157   // ceil(10000/64)

// -------------------- scratch --------------------------------------------
__device__ float g_att1[(size_t)BB * PP * AA];        // 25.7 MB
__device__ float g_c[BB * DD];
__device__ float g_xh[BB * KXH];                      // [emb | gated ctx | h]
__device__ float g_W[(size_t)NG * KXH];               // [Wih | Whh]
__device__ float g_Wdg[512 * 512];                    // [Wd ; Wfb]
__device__ float g_attp[NS_ATT * BB * 512];           // split-K partials (att2|gate)
__device__ float g_gatesp[NS_G * (size_t)BB * NG];    // split-K partials gates

// ---- 64(M)x128(N) SGEMM core, 256 threads, 4x8 micro, double-buffered ---
__device__ __forceinline__ void gemm64x128(
    const float* __restrict__ Amat, int lda,
    const float* __restrict__ Wmat, int ldw,
    int m0, int n0, int N, int kBeg, int kEnd,
    float acc[4][8])
{
    __shared__ float As[2][16][68];
    __shared__ float Bs[2][16][132];
    const int tid = threadIdx.x;
    const int ar  = tid >> 2;
    const int ak  = (tid & 3) << 2;
    const int tx  = tid & 15;
    const int ty  = tid >> 4;
    const bool okB0 = (n0 + ar)      < N;
    const bool okB1 = (n0 + ar + 64) < N;
    const float* Arow  = Amat + (size_t)(m0 + ar) * lda + ak;
    const float* Wrow0 = Wmat + (size_t)(n0 + ar) * ldw + ak;
    const float* Wrow1 = Wmat + (size_t)(n0 + ar + 64) * ldw + ak;
    const float4 f40 = make_float4(0.f, 0.f, 0.f, 0.f);

    float4 va  = *(const float4*)(Arow + kBeg);
    float4 vb0 = okB0 ? *(const float4*)(Wrow0 + kBeg) : f40;
    float4 vb1 = okB1 ? *(const float4*)(Wrow1 + kBeg) : f40;
    int buf = 0;
    As[0][ak+0][ar] = va.x;  As[0][ak+1][ar] = va.y;
    As[0][ak+2][ar] = va.z;  As[0][ak+3][ar] = va.w;
    Bs[0][ak+0][ar] = vb0.x; Bs[0][ak+1][ar] = vb0.y;
    Bs[0][ak+2][ar] = vb0.z; Bs[0][ak+3][ar] = vb0.w;
    Bs[0][ak+0][ar+64] = vb1.x; Bs[0][ak+1][ar+64] = vb1.y;
    Bs[0][ak+2][ar+64] = vb1.z; Bs[0][ak+3][ar+64] = vb1.w;
    __syncthreads();

    for (int k0 = kBeg; k0 < kEnd; k0 += 16) {
        const bool more = (k0 + 16) < kEnd;
        float4 na = f40, nb0 = f40, nb1 = f40;
        if (more) {
            na  = *(const float4*)(Arow + k0 + 16);
            if (okB0) nb0 = *(const float4*)(Wrow0 + k0 + 16);
            if (okB1) nb1 = *(const float4*)(Wrow1 + k0 + 16);
        }
        #pragma unroll
        for (int kk = 0; kk < 16; kk++) {
            float a[4], b[8];
            *(float4*)(a)     = *(const float4*)&As[buf][kk][ty << 2];
            *(float4*)(b)     = *(const float4*)&Bs[buf][kk][tx << 3];
            *(float4*)(b + 4) = *(const float4*)&Bs[buf][kk][(tx << 3) + 4];
            #pragma unroll
            for (int i = 0; i < 4; i++)
                #pragma unroll
                for (int j = 0; j < 8; j++)
                    acc[i][j] = fmaf(a[i], b[j], acc[i][j]);
        }
        if (more) {
            buf ^= 1;
            As[buf][ak+0][ar] = na.x;  As[buf][ak+1][ar] = na.y;
            As[buf][ak+2][ar] = na.z;  As[buf][ak+3][ar] = na.w;
            Bs[buf][ak+0][ar] = nb0.x; Bs[buf][ak+1][ar] = nb0.y;
            Bs[buf][ak+2][ar] = nb0.z; Bs[buf][ak+3][ar] = nb0.w;
            Bs[buf][ak+0][ar+64] = nb1.x; Bs[buf][ak+1][ar+64] = nb1.y;
            Bs[buf][ak+2][ar+64] = nb1.z; Bs[buf][ak+3][ar+64] = nb1.w;
            __syncthreads();
        }
    }
}

#define ZERO_ACC4(acc) \
    { _Pragma("unroll") for (int i = 0; i < 4; i++) \
      _Pragma("unroll") for (int j = 0; j < 8; j++) acc[i][j] = 0.f; }

__device__ __forceinline__ uint32_t f2tf32(float v) {
    uint32_t r;
    asm("cvt.rna.tf32.f32 %0, %1;" : "=r"(r) : "f"(v));
    return r;
}

__device__ __forceinline__ void mma_tf32(float c[4], const uint32_t a[4],
                                         const uint32_t b[2]) {
    asm volatile(
        "mma.sync.aligned.m16n8k8.row.col.f32.tf32.tf32.f32 "
        "{%0,%1,%2,%3}, {%4,%5,%6,%7}, {%8,%9}, {%0,%1,%2,%3};"
        : "+f"(c[0]), "+f"(c[1]), "+f"(c[2]), "+f"(c[3])
        : "r"(a[0]), "r"(a[1]), "r"(a[2]), "r"(a[3]), "r"(b[0]), "r"(b[1]));
}

// -------------------- setup: concat weights ------------------------------
__global__ __launch_bounds__(256) void concat_kernel(
    const float* __restrict__ Wih, const float* __restrict__ Whh,
    const float* __restrict__ Wd,  const float* __restrict__ Wfb)
{
    const int idx = blockIdx.x * 256 + threadIdx.x;
    if (idx < NG * KXH) {
        const int r = idx / KXH, c = idx - r * KXH;
        g_W[idx] = (c < 768) ? Wih[r * 768 + c] : Whh[r * 512 + (c - 768)];
    }
    if (idx < 512 * 512) {
        const int r = idx >> 9, c = idx & 511;
        g_Wdg[idx] = (r < 256) ? Wd[r * 512 + c] : Wfb[(r - 256) * 512 + c];
    }
}

// -------------------- setup: mean, h0, c0 --------------------------------
__global__ __launch_bounds__(256) void mean_h0c0_kernel(
    const float* __restrict__ enc,
    const float* __restrict__ Wh0, const float* __restrict__ bh0,
    const float* __restrict__ Wc0, const float* __restrict__ bc0)
{
    __shared__ float ms[EE];
    const int b = blockIdx.x, tid = threadIdx.x;
    float acc = 0.f;
    const float* eb = enc + (size_t)b * PP * EE + tid;
    #pragma unroll 4
    for (int p = 0; p < PP; p++) acc += eb[(size_t)p * EE];
    ms[tid] = acc * (1.0f / PP);
    __syncthreads();
    for (int j = tid; j < DD; j += 256) {
        float h = bh0[j], c = bc0[j];
        const float* wh = Wh0 + (size_t)j * EE;
        const float* wc = Wc0 + (size_t)j * EE;
        #pragma unroll 4
        for (int k = 0; k < EE; k++) { h = fmaf(ms[k], wh[k], h); c = fmaf(ms[k], wc[k], c); }
        g_xh[b * KXH + 768 + j] = h;
        g_c[b * DD + j] = c;
    }
}

// -------------------- setup: att1 = enc @ We^T + be ----------------------
__global__ __launch_bounds__(256) void att1_kernel(
    const float* __restrict__ enc,
    const float* __restrict__ We, const float* __restrict__ be)
{
    float acc[4][8]; ZERO_ACC4(acc);
    const int m0 = blockIdx.x * 64, n0 = blockIdx.y * 128;
    gemm64x128(enc, EE, We, EE, m0, n0, AA, 0, EE, acc);
    const int tx = threadIdx.x & 15, ty = threadIdx.x >> 4;
    #pragma unroll
    for (int i = 0; i < 4; i++) {
        const int m = m0 + (ty << 2) + i;
        #pragma unroll
        for (int j = 0; j < 8; j++) {
            const int n = n0 + (tx << 3) + j;
            g_att1[(size_t)m * AA + n] = acc[i][j] + be[n];
        }
    }
}

// -------------------- per-step: att2|gate GEMM (split-K=16) --------------
__global__ __launch_bounds__(256) void att2_kernel(
    const int* __restrict__ lengths, int t)
{
    const int m0 = blockIdx.x * 64;
    if (t >= lengths[m0] - 1) return;           // sorted desc
    const int n0 = blockIdx.y * 128;
    const int s = blockIdx.z;
    float acc[4][8]; ZERO_ACC4(acc);
    gemm64x128(g_xh + 768, KXH, g_Wdg, 512, m0, n0, 512,
               s * 32, s * 32 + 32, acc);
    float* C = g_attp + s * (BB * 512);
    const int tx = threadIdx.x & 15, ty = threadIdx.x >> 4;
    #pragma unroll
    for (int i = 0; i < 4; i++)
        #pragma unroll
        for (int j = 0; j < 8; j++)
            C[(size_t)(m0 + (ty << 2) + i) * 512 + n0 + (tx << 3) + j] = acc[i][j];
}

// -------------------- per-step: attention fused --------------------------
__global__ __launch_bounds__(512) void attn_kernel(
    const float* __restrict__ enc,
    const float* __restrict__ bd, const float* __restrict__ bfb,
    const float* __restrict__ wf, const float* __restrict__ bfp,
    const int* __restrict__ lengths, const int* __restrict__ captions,
    const float* __restrict__ embW, float* __restrict__ out_alpha, int t)
{
    __shared__ float att2_s[AA];
    __shared__ float wf_s[AA];
    __shared__ float gate_s[EE];
    __shared__ float alpha_s[256];
    __shared__ float red[16];
    __shared__ float ctxp[2][EE];
    const int b = blockIdx.x, tid = threadIdx.x;
    float* arow = out_alpha + ((size_t)b * TT + t) * PP;
    if (t >= lengths[b] - 1) {
        if (tid < PP) arow[tid] = 0.f;
        return;
    }
    if (tid < 256) {
        float a2 = bd[tid];
        #pragma unroll
        for (int s = 0; s < NS_ATT; s++) a2 += g_attp[s * (BB * 512) + b * 512 + tid];
        att2_s[tid] = a2;
        wf_s[tid] = wf[tid];
    } else {
        const int j = tid - 256;
        float gv = bfb[j];
        #pragma unroll
        for (int s = 0; s < NS_ATT; s++) gv += g_attp[s * (BB * 512) + b * 512 + 256 + j];
        gate_s[j] = 1.f / (1.f + expf(-gv));
    }
    __syncthreads();
    const float bfv = bfp[0];
    const int warp = tid >> 5, lane = tid & 31;
    {
        const float* base = g_att1 + (size_t)b * PP * AA + lane * 8;
        int p = warp;
        float4 v0 = make_float4(0,0,0,0), v1 = make_float4(0,0,0,0);
        if (p < PP) {
            v0 = *(const float4*)(base + (size_t)p * AA);
            v1 = *(const float4*)(base + (size_t)p * AA + 4);
        }
        for (; p < PP; p += 16) {
            const int pn = p + 16;
            float4 n0v = make_float4(0,0,0,0), n1v = make_float4(0,0,0,0);
            if (pn < PP) {
                n0v = *(const float4*)(base + (size_t)pn * AA);
                n1v = *(const float4*)(base + (size_t)pn * AA + 4);
            }
            const int a0 = lane * 8;
            float s = 0.f;
            s += fmaxf(v0.x + att2_s[a0 + 0], 0.f) * wf_s[a0 + 0];
            s += fmaxf(v0.y + att2_s[a0 + 1], 0.f) * wf_s[a0 + 1];
            s += fmaxf(v0.z + att2_s[a0 + 2], 0.f) * wf_s[a0 + 2];
            s += fmaxf(v0.w + att2_s[a0 + 3], 0.f) * wf_s[a0 + 3];
            s += fmaxf(v1.x + att2_s[a0 + 4], 0.f) * wf_s[a0 + 4];
            s += fmaxf(v1.y + att2_s[a0 + 5], 0.f) * wf_s[a0 + 5];
            s += fmaxf(v1.z + att2_s[a0 + 6], 0.f) * wf_s[a0 + 6];
            s += fmaxf(v1.w + att2_s[a0 + 7], 0.f) * wf_s[a0 + 7];
            #pragma unroll
            for (int off = 16; off; off >>= 1) s += __shfl_down_sync(0xffffffffu, s, off);
            if (lane == 0) alpha_s[p] = s + bfv;
            v0 = n0v; v1 = n1v;
        }
    }
    __syncthreads();
    const float sc = (tid < PP) ? alpha_s[tid] : -3.4e38f;
    float m = sc;
    #pragma unroll
    for (int off = 16; off; off >>= 1) m = fmaxf(m, __shfl_down_sync(0xffffffffu, m, off));
    if (lane == 0) red[warp] = m;
    __syncthreads();
    if (tid == 0) {
        float mm = red[0];
        #pragma unroll
        for (int i = 1; i < 16; i++) mm = fmaxf(mm, red[i]);
        red[0] = mm;
    }
    __syncthreads();
    const float mx = red[0];
    __syncthreads();
    const float ev = (tid < PP) ? expf(sc - mx) : 0.f;
    float sum = ev;
    #pragma unroll
    for (int off = 16; off; off >>= 1) sum += __shfl_down_sync(0xffffffffu, sum, off);
    if (lane == 0) red[warp] = sum;
    __syncthreads();
    if (tid == 0) {
        float ss = 0.f;
        #pragma unroll
        for (int i = 0; i < 16; i++) ss += red[i];
        red[0] = 1.f / ss;
    }
    __syncthreads();
    const float inv = red[0];
    if (tid < PP) {
        const float al = ev * inv;
        alpha_s[tid] = al;
        arow[tid] = al;
    }
    __syncthreads();
    {
        const int e = tid & 255, half = tid >> 8;
        const int pB = half * 98, pE = pB + 98;
        float acc = 0.f;
        const float* eb = enc + (size_t)b * PP * EE + e;
        #pragma unroll 8
        for (int p = pB; p < pE; p++) acc = fmaf(eb[(size_t)p * EE], alpha_s[p], acc);
        ctxp[half][e] = acc;
    }
    __syncthreads();
    if (tid < 256)
        g_xh[b * KXH + 512 + tid] = (ctxp[0][tid] + ctxp[1][tid]) * gate_s[tid];
    {
        const int cap = captions[b * LL + t];
        g_xh[b * KXH + tid] = embW[(size_t)cap * MME + tid];
    }
}

// -------------------- per-step: fused gates GEMM (split-K=5) -------------
__global__ __launch_bounds__(256) void gates_kernel(
    const int* __restrict__ lengths, int t)
{
    const int m0 = blockIdx.x * 64;
    if (t >= lengths[m0] - 1) return;
    const int n0 = blockIdx.y * 128;
    const int s = blockIdx.z;
    float acc[4][8]; ZERO_ACC4(acc);
    gemm64x128(g_xh, KXH, g_W, KXH, m0, n0, NG, s * 256, s * 256 + 256, acc);
    float* C = g_gatesp + (size_t)s * (BB * NG);
    const int tx = threadIdx.x & 15, ty = threadIdx.x >> 4;
    #pragma unroll
    for (int i = 0; i < 4; i++)
        #pragma unroll
        for (int j = 0; j < 8; j++)
            C[(size_t)(m0 + (ty << 2) + i) * NG + n0 + (tx << 3) + j] = acc[i][j];
}

// -------------------- per-step: LSTM pointwise (reduce + act) ------------
__global__ __launch_bounds__(512) void lstm_kernel(
    const float* __restrict__ bih, const float* __restrict__ bhh,
    const int* __restrict__ lengths, int t)
{
    const int b = blockIdx.x, d = threadIdx.x;
    if (t >= lengths[b] - 1) return;
    float v[4];
    #pragma unroll
    for (int g = 0; g < 4; g++) {
        const int n = g * DD + d;
        float x = bih[n] + bhh[n];
        #pragma unroll
        for (int s = 0; s < NS_G; s++)
            x += g_gatesp[(size_t)s * (BB * NG) + (size_t)b * NG + n];
        v[g] = x;
    }
    const float c  = g_c[b * DD + d];
    const float si = 1.f / (1.f + expf(-v[0]));
    const float sf = 1.f / (1.f + expf(-v[1]));
    const float so = 1.f / (1.f + expf(-v[3]));
    const float cn = sf * c + si * tanhf(v[2]);
    const float hn = so * tanhf(cn);
    g_c[b * DD + d] = cn;
    g_xh[b * KXH + 768 + d] = hn;
}

// -------------------- per-step: vocab projection (tf32 tensor cores) -----
// C[128, VV] = H[128,512] @ Wfc[VV,512]^T + bfc, masked.
// BM=128, BN=64, BK=32. 256 threads = 8 warps; warp tile 32(M)x32(N).
__global__ __launch_bounds__(256) void pred_tf32_kernel(
    const float* __restrict__ Wfc, const float* __restrict__ bfc,
    const int* __restrict__ lengths, float* __restrict__ out, int t)
{
    __shared__ uint32_t As[128][36];
    __shared__ uint32_t Bs[64][36];
    __shared__ int len_s[BB];
    const int tid  = threadIdx.x;
    const int wid  = tid >> 5, lane = tid & 31;
    const int gr   = lane >> 2, ct = lane & 3;
    const int wm   = (wid & 3) * 32;     // warp M base
    const int wn   = (wid >> 2) * 32;    // warp N base
    const int n0   = blockIdx.x * PRED_BN;
    const float* H = g_xh + 768;

    if (tid < BB) len_s[tid] = lengths[tid];

    float acc[2][4][4];
    #pragma unroll
    for (int mt = 0; mt < 2; mt++)
        #pragma unroll
        for (int nt = 0; nt < 4; nt++)
            #pragma unroll
            for (int r = 0; r < 4; r++) acc[mt][nt][r] = 0.f;

    for (int kb = 0; kb < DD; kb += 32) {
        __syncthreads();   // protect previous tile consumption (and len_s on iter 0)
        // stage A: 128x32 (1024 float4) — 4 per thread
        #pragma unroll
        for (int i = 0; i < 4; i++) {
            const int idx = tid + i * 256;
            const int r = idx >> 3, c = (idx & 7) << 2;
            float4 v = *(const float4*)(H + (size_t)r * KXH + kb + c);
            As[r][c + 0] = f2tf32(v.x); As[r][c + 1] = f2tf32(v.y);
            As[r][c + 2] = f2tf32(v.z); As[r][c + 3] = f2tf32(v.w);
        }
        // stage B: 64x32 (512 float4) — 2 per thread
        #pragma unroll
        for (int i = 0; i < 2; i++) {
            const int idx = tid + i * 256;
            const int r = idx >> 3, c = (idx & 7) << 2;
            const int n = n0 + r;
            float4 v = (n < VV) ? *(const float4*)(Wfc + (size_t)n * DD + kb + c)
                                : make_float4(0.f, 0.f, 0.f, 0.f);
            Bs[r][c + 0] = f2tf32(v.x); Bs[r][c + 1] = f2tf32(v.y);
            Bs[r][c + 2] = f2tf32(v.z); Bs[r][c + 3] = f2tf32(v.w);
        }
        __syncthreads();
        #pragma unroll
        for (int ks = 0; ks < 32; ks += 8) {
            uint32_t a[2][4], b[4][2];
            #pragma unroll
            for (int mt = 0; mt < 2; mt++) {
                const int row = wm + mt * 16 + gr;
                a[mt][0] = As[row][ks + ct];
                a[mt][1] = As[row + 8][ks + ct];
                a[mt][2] = As[row][ks + ct + 4];
                a[mt][3] = As[row + 8][ks + ct + 4];
            }
            #pragma unroll
            for (int nt = 0; nt < 4; nt++) {
                const int rn = wn + nt * 8 + gr;
                b[nt][0] = Bs[rn][ks + ct];
                b[nt][1] = Bs[rn][ks + ct + 4];
            }
            #pragma unroll
            for (int mt = 0; mt < 2; mt++)
                #pragma unroll
                for (int nt = 0; nt < 4; nt++)
                    mma_tf32(acc[mt][nt], a[mt], b[nt]);
        }
    }

    // epilogue: C fragment (gr,2ct),(gr,2ct+1),(gr+8,2ct),(gr+8,2ct+1)
    #pragma unroll
    for (int mt = 0; mt < 2; mt++) {
        const int r0 = wm + mt * 16 + gr;
        const int r1 = r0 + 8;
        const bool act0 = t < len_s[r0] - 1;
        const bool act1 = t < len_s[r1] - 1;
        #pragma unroll
        for (int nt = 0; nt < 4; nt++) {
            const int col = n0 + wn + nt * 8 + 2 * ct;
            if (col < VV) {
                const float bz0 = bfc[col];
                out[((size_t)r0 * TT + t) * VV + col] = act0 ? (acc[mt][nt][0] + bz0) : 0.f;
                out[((size_t)r1 * TT + t) * VV + col] = act1 ? (acc[mt][nt][2] + bz0) : 0.f;
            }
            if (col + 1 < VV) {
                const float bz1 = bfc[col + 1];
                out[((size_t)r0 * TT + t) * VV + col + 1] = act0 ? (acc[mt][nt][1] + bz1) : 0.f;
                out[((size_t)r1 * TT + t) * VV + col + 1] = act1 ? (acc[mt][nt][3] + bz1) : 0.f;
            }
        }
    }
}

// -------------------- launch -------------------------------------------
extern "C" void kernel_launch(void* const* d_in, const int* in_sizes, int n_in,
                              void* d_out, int out_size) {
    const float* enc      = (const float*)d_in[0];
    const int*   captions = (const int*)  d_in[1];
    const int*   lengths  = (const int*)  d_in[2];
    const float* embW     = (const float*)d_in[3];
    const float* We       = (const float*)d_in[4];
    const float* be       = (const float*)d_in[5];
    const float* Wd       = (const float*)d_in[6];
    const float* bd       = (const float*)d_in[7];
    const float* wf       = (const float*)d_in[8];
    const float* bf       = (const float*)d_in[9];
    const float* Wih      = (const float*)d_in[10];
    const float* bih      = (const float*)d_in[11];
    const float* Whh      = (const float*)d_in[12];
    const float* bhh      = (const float*)d_in[13];
    const float* Wh0      = (const float*)d_in[14];
    const float* bh0      = (const float*)d_in[15];
    const float* Wc0      = (const float*)d_in[16];
    const float* bc0      = (const float*)d_in[17];
    const float* Wfb      = (const float*)d_in[18];
    const float* bfb      = (const float*)d_in[19];
    const float* Wfc      = (const float*)d_in[20];
    const float* bfc      = (const float*)d_in[21];

    float* out_pred  = (float*)d_out;
    float* out_alpha = out_pred + (size_t)BB * TT * VV;

    concat_kernel<<<(NG * KXH + 255) / 256, 256>>>(Wih, Whh, Wd, Wfb);
    mean_h0c0_kernel<<<BB, 256>>>(enc, Wh0, bh0, Wc0, bc0);
    att1_kernel<<<dim3((BB * PP) / 64, AA / 128), 256>>>(enc, We, be);

    for (int t = 0; t < TT; t++) {
        att2_kernel<<<dim3(2, 4, NS_ATT), 256>>>(lengths, t);
        attn_kernel<<<BB, 512>>>(enc, bd, bfb, wf, bf, lengths, captions,
                                 embW, out_alpha, t);
        gates_kernel<<<dim3(2, NG / 128, NS_G), 256>>>(lengths, t);
        lstm_kernel<<<BB, 512>>>(bih, bhh, lengths, t);
        pred_tf32_kernel<<<PRED_GRID, 256>>>(Wfc, bfc, lengths, out_pred, t);
    }
}

// round 7
// speedup vs baseline: 4.9341x; 1.3012x over previous
#include <cuda_runtime.h>
#include <math.h>
#include <stdint.h>

// Problem dims
#define BB 128
#define PP 196
#define EE 256
#define AA 256
#define DD 512
#define MME 512
#define VV 10000
#define LL 26
#define TT 25
#define KXH 1280     // emb(512) | ctx(256) | h(512)
#define NG  2048     // 4*DD gates
#define NS_ATT 16    // split-K for att2
#define NS_G   5     // split-K for gates
#define PRED_BN 64
#define PRED_GRID 157   // ceil(10000/64)

// -------------------- scratch --------------------------------------------
__device__ float g_att1[(size_t)BB * PP * AA];        // 25.7 MB
__device__ float g_c[BB * DD];
__device__ float g_xh[BB * KXH];                      // [emb | gated ctx | h]
__device__ float g_W[(size_t)NG * KXH];               // [Wih | Whh]
__device__ float g_Wdg[512 * 512];                    // [Wd ; Wfb]
__device__ float g_attp[NS_ATT * BB * 512];           // split-K partials (att2|gate)
__device__ float g_gatesp[NS_G * (size_t)BB * NG];    // split-K partials gates

// ---- 64(M)x128(N) fp32 SGEMM core (setup kernels only) ------------------
__device__ __forceinline__ void gemm64x128(
    const float* __restrict__ Amat, int lda,
    const float* __restrict__ Wmat, int ldw,
    int m0, int n0, int N, int kBeg, int kEnd,
    float acc[4][8])
{
    __shared__ float As[2][16][68];
    __shared__ float Bs[2][16][132];
    const int tid = threadIdx.x;
    const int ar  = tid >> 2;
    const int ak  = (tid & 3) << 2;
    const int tx  = tid & 15;
    const int ty  = tid >> 4;
    const bool okB0 = (n0 + ar)      < N;
    const bool okB1 = (n0 + ar + 64) < N;
    const float* Arow  = Amat + (size_t)(m0 + ar) * lda + ak;
    const float* Wrow0 = Wmat + (size_t)(n0 + ar) * ldw + ak;
    const float* Wrow1 = Wmat + (size_t)(n0 + ar + 64) * ldw + ak;
    const float4 f40 = make_float4(0.f, 0.f, 0.f, 0.f);

    float4 va  = *(const float4*)(Arow + kBeg);
    float4 vb0 = okB0 ? *(const float4*)(Wrow0 + kBeg) : f40;
    float4 vb1 = okB1 ? *(const float4*)(Wrow1 + kBeg) : f40;
    int buf = 0;
    As[0][ak+0][ar] = va.x;  As[0][ak+1][ar] = va.y;
    As[0][ak+2][ar] = va.z;  As[0][ak+3][ar] = va.w;
    Bs[0][ak+0][ar] = vb0.x; Bs[0][ak+1][ar] = vb0.y;
    Bs[0][ak+2][ar] = vb0.z; Bs[0][ak+3][ar] = vb0.w;
    Bs[0][ak+0][ar+64] = vb1.x; Bs[0][ak+1][ar+64] = vb1.y;
    Bs[0][ak+2][ar+64] = vb1.z; Bs[0][ak+3][ar+64] = vb1.w;
    __syncthreads();

    for (int k0 = kBeg; k0 < kEnd; k0 += 16) {
        const bool more = (k0 + 16) < kEnd;
        float4 na = f40, nb0 = f40, nb1 = f40;
        if (more) {
            na  = *(const float4*)(Arow + k0 + 16);
            if (okB0) nb0 = *(const float4*)(Wrow0 + k0 + 16);
            if (okB1) nb1 = *(const float4*)(Wrow1 + k0 + 16);
        }
        #pragma unroll
        for (int kk = 0; kk < 16; kk++) {
            float a[4], b[8];
            *(float4*)(a)     = *(const float4*)&As[buf][kk][ty << 2];
            *(float4*)(b)     = *(const float4*)&Bs[buf][kk][tx << 3];
            *(float4*)(b + 4) = *(const float4*)&Bs[buf][kk][(tx << 3) + 4];
            #pragma unroll
            for (int i = 0; i < 4; i++)
                #pragma unroll
                for (int j = 0; j < 8; j++)
                    acc[i][j] = fmaf(a[i], b[j], acc[i][j]);
        }
        if (more) {
            buf ^= 1;
            As[buf][ak+0][ar] = na.x;  As[buf][ak+1][ar] = na.y;
            As[buf][ak+2][ar] = na.z;  As[buf][ak+3][ar] = na.w;
            Bs[buf][ak+0][ar] = nb0.x; Bs[buf][ak+1][ar] = nb0.y;
            Bs[buf][ak+2][ar] = nb0.z; Bs[buf][ak+3][ar] = nb0.w;
            Bs[buf][ak+0][ar+64] = nb1.x; Bs[buf][ak+1][ar+64] = nb1.y;
            Bs[buf][ak+2][ar+64] = nb1.z; Bs[buf][ak+3][ar+64] = nb1.w;
            __syncthreads();
        }
    }
}

#define ZERO_ACC4(acc) \
    { _Pragma("unroll") for (int i = 0; i < 4; i++) \
      _Pragma("unroll") for (int j = 0; j < 8; j++) acc[i][j] = 0.f; }

__device__ __forceinline__ uint32_t f2tf32(float v) {
    uint32_t r;
    asm("cvt.rna.tf32.f32 %0, %1;" : "=r"(r) : "f"(v));
    return r;
}

__device__ __forceinline__ void mma_tf32(float c[4], const uint32_t a[4],
                                         const uint32_t b[2]) {
    asm volatile(
        "mma.sync.aligned.m16n8k8.row.col.f32.tf32.tf32.f32 "
        "{%0,%1,%2,%3}, {%4,%5,%6,%7}, {%8,%9}, {%0,%1,%2,%3};"
        : "+f"(c[0]), "+f"(c[1]), "+f"(c[2]), "+f"(c[3])
        : "r"(a[0]), "r"(a[1]), "r"(a[2]), "r"(a[3]), "r"(b[0]), "r"(b[1]));
}

// ---- 128(M) x 64(N) tf32x3 GEMM body: near-fp32 precision ----------------
// acc += A[0:128, kBeg:kEnd] @ W[n0:n0+64, kBeg:kEnd]^T  (256 threads)
// Warp w: M base (w&3)*32, N base (w>>2)*32; frag layout as pred kernel.
__device__ __forceinline__ void gemm_tf32x3(
    const float* __restrict__ A, int lda,
    const float* __restrict__ W, int ldw,
    int n0, int kBeg, int kEnd,
    float acc[2][4][4])
{
    __shared__ float As[128][36];
    __shared__ float Bs[64][36];
    const int tid = threadIdx.x;
    const int wid = tid >> 5, lane = tid & 31;
    const int gr = lane >> 2, ct = lane & 3;
    const int wm = (wid & 3) * 32;
    const int wn = (wid >> 2) * 32;

    for (int kb = kBeg; kb < kEnd; kb += 32) {
        __syncthreads();
        #pragma unroll
        for (int i = 0; i < 4; i++) {
            const int idx = tid + i * 256;
            const int r = idx >> 3, c = (idx & 7) << 2;
            float4 v = *(const float4*)(A + (size_t)r * lda + kb + c);
            As[r][c+0] = v.x; As[r][c+1] = v.y; As[r][c+2] = v.z; As[r][c+3] = v.w;
        }
        #pragma unroll
        for (int i = 0; i < 2; i++) {
            const int idx = tid + i * 256;
            const int r = idx >> 3, c = (idx & 7) << 2;
            float4 v = *(const float4*)(W + (size_t)(n0 + r) * ldw + kb + c);
            Bs[r][c+0] = v.x; Bs[r][c+1] = v.y; Bs[r][c+2] = v.z; Bs[r][c+3] = v.w;
        }
        __syncthreads();
        #pragma unroll
        for (int ks = 0; ks < 32; ks += 8) {
            uint32_t ah[2][4], al[2][4], bh[4][2], bl[4][2];
            #pragma unroll
            for (int mt = 0; mt < 2; mt++) {
                const int row = wm + mt * 16 + gr;
                float f0 = As[row][ks+ct],     f1 = As[row+8][ks+ct];
                float f2 = As[row][ks+ct+4],   f3 = As[row+8][ks+ct+4];
                ah[mt][0] = f2tf32(f0); al[mt][0] = f2tf32(f0 - __uint_as_float(ah[mt][0]));
                ah[mt][1] = f2tf32(f1); al[mt][1] = f2tf32(f1 - __uint_as_float(ah[mt][1]));
                ah[mt][2] = f2tf32(f2); al[mt][2] = f2tf32(f2 - __uint_as_float(ah[mt][2]));
                ah[mt][3] = f2tf32(f3); al[mt][3] = f2tf32(f3 - __uint_as_float(ah[mt][3]));
            }
            #pragma unroll
            for (int nt = 0; nt < 4; nt++) {
                const int rn = wn + nt * 8 + gr;
                float f0 = Bs[rn][ks+ct], f1 = Bs[rn][ks+ct+4];
                bh[nt][0] = f2tf32(f0); bl[nt][0] = f2tf32(f0 - __uint_as_float(bh[nt][0]));
                bh[nt][1] = f2tf32(f1); bl[nt][1] = f2tf32(f1 - __uint_as_float(bh[nt][1]));
            }
            #pragma unroll
            for (int mt = 0; mt < 2; mt++)
                #pragma unroll
                for (int nt = 0; nt < 4; nt++) {
                    mma_tf32(acc[mt][nt], ah[mt], bh[nt]);
                    mma_tf32(acc[mt][nt], ah[mt], bl[nt]);
                    mma_tf32(acc[mt][nt], al[mt], bh[nt]);
                }
        }
    }
}

#define ZERO_ACC244(acc) \
    { _Pragma("unroll") for (int mt = 0; mt < 2; mt++) \
      _Pragma("unroll") for (int nt = 0; nt < 4; nt++) \
      _Pragma("unroll") for (int r = 0; r < 4; r++) acc[mt][nt][r] = 0.f; }

// -------------------- setup: concat weights ------------------------------
__global__ __launch_bounds__(256) void concat_kernel(
    const float* __restrict__ Wih, const float* __restrict__ Whh,
    const float* __restrict__ Wd,  const float* __restrict__ Wfb)
{
    const int idx = blockIdx.x * 256 + threadIdx.x;
    if (idx < NG * KXH) {
        const int r = idx / KXH, c = idx - r * KXH;
        g_W[idx] = (c < 768) ? Wih[r * 768 + c] : Whh[r * 512 + (c - 768)];
    }
    if (idx < 512 * 512) {
        const int r = idx >> 9, c = idx & 511;
        g_Wdg[idx] = (r < 256) ? Wd[r * 512 + c] : Wfb[(r - 256) * 512 + c];
    }
}

// -------------------- setup: mean, h0, c0 --------------------------------
__global__ __launch_bounds__(256) void mean_h0c0_kernel(
    const float* __restrict__ enc,
    const float* __restrict__ Wh0, const float* __restrict__ bh0,
    const float* __restrict__ Wc0, const float* __restrict__ bc0)
{
    __shared__ float ms[EE];
    const int b = blockIdx.x, tid = threadIdx.x;
    float acc = 0.f;
    const float* eb = enc + (size_t)b * PP * EE + tid;
    #pragma unroll 4
    for (int p = 0; p < PP; p++) acc += eb[(size_t)p * EE];
    ms[tid] = acc * (1.0f / PP);
    __syncthreads();
    for (int j = tid; j < DD; j += 256) {
        float h = bh0[j], c = bc0[j];
        const float* wh = Wh0 + (size_t)j * EE;
        const float* wc = Wc0 + (size_t)j * EE;
        #pragma unroll 4
        for (int k = 0; k < EE; k++) { h = fmaf(ms[k], wh[k], h); c = fmaf(ms[k], wc[k], c); }
        g_xh[b * KXH + 768 + j] = h;
        g_c[b * DD + j] = c;
    }
}

// -------------------- setup: att1 = enc @ We^T + be ----------------------
__global__ __launch_bounds__(256) void att1_kernel(
    const float* __restrict__ enc,
    const float* __restrict__ We, const float* __restrict__ be)
{
    float acc[4][8]; ZERO_ACC4(acc);
    const int m0 = blockIdx.x * 64, n0 = blockIdx.y * 128;
    gemm64x128(enc, EE, We, EE, m0, n0, AA, 0, EE, acc);
    const int tx = threadIdx.x & 15, ty = threadIdx.x >> 4;
    #pragma unroll
    for (int i = 0; i < 4; i++) {
        const int m = m0 + (ty << 2) + i;
        #pragma unroll
        for (int j = 0; j < 8; j++) {
            const int n = n0 + (tx << 3) + j;
            g_att1[(size_t)m * AA + n] = acc[i][j] + be[n];
        }
    }
}

// ---------- per-step: att2|gate GEMM (tf32x3, split-K=16) ----------------
// C[128,512] = H[128,512] @ Wdg[512,512]^T ; block: n0 = bx*64, k = by*32
__global__ __launch_bounds__(256) void att2_tf32_kernel(int t)
{
    float acc[2][4][4]; ZERO_ACC244(acc);
    const int n0 = blockIdx.x * 64;
    const int s  = blockIdx.y;
    gemm_tf32x3(g_xh + 768, KXH, g_Wdg, 512, n0, s * 32, s * 32 + 32, acc);
    float* C = g_attp + s * (BB * 512);
    const int tid = threadIdx.x, wid = tid >> 5, lane = tid & 31;
    const int gr = lane >> 2, ct = lane & 3;
    const int wm = (wid & 3) * 32, wn = (wid >> 2) * 32;
    #pragma unroll
    for (int mt = 0; mt < 2; mt++) {
        const int r0 = wm + mt * 16 + gr, r1 = r0 + 8;
        #pragma unroll
        for (int nt = 0; nt < 4; nt++) {
            const int col = n0 + wn + nt * 8 + 2 * ct;
            C[(size_t)r0 * 512 + col]     = acc[mt][nt][0];
            C[(size_t)r0 * 512 + col + 1] = acc[mt][nt][1];
            C[(size_t)r1 * 512 + col]     = acc[mt][nt][2];
            C[(size_t)r1 * 512 + col + 1] = acc[mt][nt][3];
        }
    }
}

// ---------- per-step: fused gates GEMM (tf32x3, split-K=5) ---------------
// C[128,2048] = XH[128,1280] @ W[2048,1280]^T ; n0 = bx*64, k = by*256
__global__ __launch_bounds__(256) void gates_tf32_kernel(int t)
{
    float acc[2][4][4]; ZERO_ACC244(acc);
    const int n0 = blockIdx.x * 64;
    const int s  = blockIdx.y;
    gemm_tf32x3(g_xh, KXH, g_W, KXH, n0, s * 256, s * 256 + 256, acc);
    float* C = g_gatesp + (size_t)s * (BB * NG);
    const int tid = threadIdx.x, wid = tid >> 5, lane = tid & 31;
    const int gr = lane >> 2, ct = lane & 3;
    const int wm = (wid & 3) * 32, wn = (wid >> 2) * 32;
    #pragma unroll
    for (int mt = 0; mt < 2; mt++) {
        const int r0 = wm + mt * 16 + gr, r1 = r0 + 8;
        #pragma unroll
        for (int nt = 0; nt < 4; nt++) {
            const int col = n0 + wn + nt * 8 + 2 * ct;
            C[(size_t)r0 * NG + col]     = acc[mt][nt][0];
            C[(size_t)r0 * NG + col + 1] = acc[mt][nt][1];
            C[(size_t)r1 * NG + col]     = acc[mt][nt][2];
            C[(size_t)r1 * NG + col + 1] = acc[mt][nt][3];
        }
    }
}

// -------------------- per-step: attention fused --------------------------
__global__ __launch_bounds__(512) void attn_kernel(
    const float* __restrict__ enc,
    const float* __restrict__ bd, const float* __restrict__ bfb,
    const float* __restrict__ wf, const float* __restrict__ bfp,
    const int* __restrict__ lengths, const int* __restrict__ captions,
    const float* __restrict__ embW, float* __restrict__ out_alpha, int t)
{
    __shared__ float att2_s[AA];
    __shared__ float wf_s[AA];
    __shared__ float gate_s[EE];
    __shared__ float alpha_s[256];
    __shared__ float red[16];
    __shared__ float ctxp[2][EE];
    const int b = blockIdx.x, tid = threadIdx.x;
    float* arow = out_alpha + ((size_t)b * TT + t) * PP;
    if (t >= lengths[b] - 1) {
        if (tid < PP) arow[tid] = 0.f;
        return;
    }
    if (tid < 256) {
        float a2 = bd[tid];
        #pragma unroll
        for (int s = 0; s < NS_ATT; s++) a2 += g_attp[s * (BB * 512) + b * 512 + tid];
        att2_s[tid] = a2;
        wf_s[tid] = wf[tid];
    } else {
        const int j = tid - 256;
        float gv = bfb[j];
        #pragma unroll
        for (int s = 0; s < NS_ATT; s++) gv += g_attp[s * (BB * 512) + b * 512 + 256 + j];
        gate_s[j] = 1.f / (1.f + expf(-gv));
    }
    __syncthreads();
    const float bfv = bfp[0];
    const int warp = tid >> 5, lane = tid & 31;
    {
        const float* base = g_att1 + (size_t)b * PP * AA + lane * 8;
        int p = warp;
        float4 v0 = make_float4(0,0,0,0), v1 = make_float4(0,0,0,0);
        if (p < PP) {
            v0 = *(const float4*)(base + (size_t)p * AA);
            v1 = *(const float4*)(base + (size_t)p * AA + 4);
        }
        for (; p < PP; p += 16) {
            const int pn = p + 16;
            float4 n0v = make_float4(0,0,0,0), n1v = make_float4(0,0,0,0);
            if (pn < PP) {
                n0v = *(const float4*)(base + (size_t)pn * AA);
                n1v = *(const float4*)(base + (size_t)pn * AA + 4);
            }
            const int a0 = lane * 8;
            float s = 0.f;
            s += fmaxf(v0.x + att2_s[a0 + 0], 0.f) * wf_s[a0 + 0];
            s += fmaxf(v0.y + att2_s[a0 + 1], 0.f) * wf_s[a0 + 1];
            s += fmaxf(v0.z + att2_s[a0 + 2], 0.f) * wf_s[a0 + 2];
            s += fmaxf(v0.w + att2_s[a0 + 3], 0.f) * wf_s[a0 + 3];
            s += fmaxf(v1.x + att2_s[a0 + 4], 0.f) * wf_s[a0 + 4];
            s += fmaxf(v1.y + att2_s[a0 + 5], 0.f) * wf_s[a0 + 5];
            s += fmaxf(v1.z + att2_s[a0 + 6], 0.f) * wf_s[a0 + 6];
            s += fmaxf(v1.w + att2_s[a0 + 7], 0.f) * wf_s[a0 + 7];
            #pragma unroll
            for (int off = 16; off; off >>= 1) s += __shfl_down_sync(0xffffffffu, s, off);
            if (lane == 0) alpha_s[p] = s + bfv;
            v0 = n0v; v1 = n1v;
        }
    }
    __syncthreads();
    const float sc = (tid < PP) ? alpha_s[tid] : -3.4e38f;
    float m = sc;
    #pragma unroll
    for (int off = 16; off; off >>= 1) m = fmaxf(m, __shfl_down_sync(0xffffffffu, m, off));
    if (lane == 0) red[warp] = m;
    __syncthreads();
    if (tid == 0) {
        float mm = red[0];
        #pragma unroll
        for (int i = 1; i < 16; i++) mm = fmaxf(mm, red[i]);
        red[0] = mm;
    }
    __syncthreads();
    const float mx = red[0];
    __syncthreads();
    const float ev = (tid < PP) ? expf(sc - mx) : 0.f;
    float sum = ev;
    #pragma unroll
    for (int off = 16; off; off >>= 1) sum += __shfl_down_sync(0xffffffffu, sum, off);
    if (lane == 0) red[warp] = sum;
    __syncthreads();
    if (tid == 0) {
        float ss = 0.f;
        #pragma unroll
        for (int i = 0; i < 16; i++) ss += red[i];
        red[0] = 1.f / ss;
    }
    __syncthreads();
    const float inv = red[0];
    if (tid < PP) {
        const float al = ev * inv;
        alpha_s[tid] = al;
        arow[tid] = al;
    }
    __syncthreads();
    {
        const int e = tid & 255, half = tid >> 8;
        const int pB = half * 98, pE = pB + 98;
        float acc = 0.f;
        const float* eb = enc + (size_t)b * PP * EE + e;
        #pragma unroll 8
        for (int p = pB; p < pE; p++) acc = fmaf(eb[(size_t)p * EE], alpha_s[p], acc);
        ctxp[half][e] = acc;
    }
    __syncthreads();
    if (tid < 256)
        g_xh[b * KXH + 512 + tid] = (ctxp[0][tid] + ctxp[1][tid]) * gate_s[tid];
    {
        const int cap = captions[b * LL + t];
        g_xh[b * KXH + tid] = embW[(size_t)cap * MME + tid];
    }
}

// -------------------- per-step: LSTM pointwise (reduce + act) ------------
__global__ __launch_bounds__(512) void lstm_kernel(
    const float* __restrict__ bih, const float* __restrict__ bhh,
    const int* __restrict__ lengths, int t)
{
    const int b = blockIdx.x, d = threadIdx.x;
    if (t >= lengths[b] - 1) return;
    float v[4];
    #pragma unroll
    for (int g = 0; g < 4; g++) {
        const int n = g * DD + d;
        float x = bih[n] + bhh[n];
        #pragma unroll
        for (int s = 0; s < NS_G; s++)
            x += g_gatesp[(size_t)s * (BB * NG) + (size_t)b * NG + n];
        v[g] = x;
    }
    const float c  = g_c[b * DD + d];
    const float si = 1.f / (1.f + expf(-v[0]));
    const float sf = 1.f / (1.f + expf(-v[1]));
    const float so = 1.f / (1.f + expf(-v[3]));
    const float cn = sf * c + si * tanhf(v[2]);
    const float hn = so * tanhf(cn);
    g_c[b * DD + d] = cn;
    g_xh[b * KXH + 768 + d] = hn;
}

// -------------------- per-step: vocab projection (tf32 tensor cores) -----
__global__ __launch_bounds__(256) void pred_tf32_kernel(
    const float* __restrict__ Wfc, const float* __restrict__ bfc,
    const int* __restrict__ lengths, float* __restrict__ out, int t)
{
    __shared__ uint32_t As[128][36];
    __shared__ uint32_t Bs[64][36];
    __shared__ int len_s[BB];
    const int tid  = threadIdx.x;
    const int wid  = tid >> 5, lane = tid & 31;
    const int gr   = lane >> 2, ct = lane & 3;
    const int wm   = (wid & 3) * 32;
    const int wn   = (wid >> 2) * 32;
    const int n0   = blockIdx.x * PRED_BN;
    const float* H = g_xh + 768;

    if (tid < BB) len_s[tid] = lengths[tid];

    float acc[2][4][4];
    #pragma unroll
    for (int mt = 0; mt < 2; mt++)
        #pragma unroll
        for (int nt = 0; nt < 4; nt++)
            #pragma unroll
            for (int r = 0; r < 4; r++) acc[mt][nt][r] = 0.f;

    for (int kb = 0; kb < DD; kb += 32) {
        __syncthreads();
        #pragma unroll
        for (int i = 0; i < 4; i++) {
            const int idx = tid + i * 256;
            const int r = idx >> 3, c = (idx & 7) << 2;
            float4 v = *(const float4*)(H + (size_t)r * KXH + kb + c);
            As[r][c + 0] = f2tf32(v.x); As[r][c + 1] = f2tf32(v.y);
            As[r][c + 2] = f2tf32(v.z); As[r][c + 3] = f2tf32(v.w);
        }
        #pragma unroll
        for (int i = 0; i < 2; i++) {
            const int idx = tid + i * 256;
            const int r = idx >> 3, c = (idx & 7) << 2;
            const int n = n0 + r;
            float4 v = (n < VV) ? *(const float4*)(Wfc + (size_t)n * DD + kb + c)
                                : make_float4(0.f, 0.f, 0.f, 0.f);
            Bs[r][c + 0] = f2tf32(v.x); Bs[r][c + 1] = f2tf32(v.y);
            Bs[r][c + 2] = f2tf32(v.z); Bs[r][c + 3] = f2tf32(v.w);
        }
        __syncthreads();
        #pragma unroll
        for (int ks = 0; ks < 32; ks += 8) {
            uint32_t a[2][4], b[4][2];
            #pragma unroll
            for (int mt = 0; mt < 2; mt++) {
                const int row = wm + mt * 16 + gr;
                a[mt][0] = As[row][ks + ct];
                a[mt][1] = As[row + 8][ks + ct];
                a[mt][2] = As[row][ks + ct + 4];
                a[mt][3] = As[row + 8][ks + ct + 4];
            }
            #pragma unroll
            for (int nt = 0; nt < 4; nt++) {
                const int rn = wn + nt * 8 + gr;
                b[nt][0] = Bs[rn][ks + ct];
                b[nt][1] = Bs[rn][ks + ct + 4];
            }
            #pragma unroll
            for (int mt = 0; mt < 2; mt++)
                #pragma unroll
                for (int nt = 0; nt < 4; nt++)
                    mma_tf32(acc[mt][nt], a[mt], b[nt]);
        }
    }

    #pragma unroll
    for (int mt = 0; mt < 2; mt++) {
        const int r0 = wm + mt * 16 + gr;
        const int r1 = r0 + 8;
        const bool act0 = t < len_s[r0] - 1;
        const bool act1 = t < len_s[r1] - 1;
        #pragma unroll
        for (int nt = 0; nt < 4; nt++) {
            const int col = n0 + wn + nt * 8 + 2 * ct;
            if (col < VV) {
                const float bz0 = bfc[col];
                out[((size_t)r0 * TT + t) * VV + col] = act0 ? (acc[mt][nt][0] + bz0) : 0.f;
                out[((size_t)r1 * TT + t) * VV + col] = act1 ? (acc[mt][nt][2] + bz0) : 0.f;
            }
            if (col + 1 < VV) {
                const float bz1 = bfc[col + 1];
                out[((size_t)r0 * TT + t) * VV + col + 1] = act0 ? (acc[mt][nt][1] + bz1) : 0.f;
                out[((size_t)r1 * TT + t) * VV + col + 1] = act1 ? (acc[mt][nt][3] + bz1) : 0.f;
            }
        }
    }
}

// -------------------- launch -------------------------------------------
extern "C" void kernel_launch(void* const* d_in, const int* in_sizes, int n_in,
                              void* d_out, int out_size) {
    const float* enc      = (const float*)d_in[0];
    const int*   captions = (const int*)  d_in[1];
    const int*   lengths  = (const int*)  d_in[2];
    const float* embW     = (const float*)d_in[3];
    const float* We       = (const float*)d_in[4];
    const float* be       = (const float*)d_in[5];
    const float* Wd       = (const float*)d_in[6];
    const float* bd       = (const float*)d_in[7];
    const float* wf       = (const float*)d_in[8];
    const float* bf       = (const float*)d_in[9];
    const float* Wih      = (const float*)d_in[10];
    const float* bih      = (const float*)d_in[11];
    const float* Whh      = (const float*)d_in[12];
    const float* bhh      = (const float*)d_in[13];
    const float* Wh0      = (const float*)d_in[14];
    const float* bh0      = (const float*)d_in[15];
    const float* Wc0      = (const float*)d_in[16];
    const float* bc0      = (const float*)d_in[17];
    const float* Wfb      = (const float*)d_in[18];
    const float* bfb      = (const float*)d_in[19];
    const float* Wfc      = (const float*)d_in[20];
    const float* bfc      = (const float*)d_in[21];

    float* out_pred  = (float*)d_out;
    float* out_alpha = out_pred + (size_t)BB * TT * VV;

    concat_kernel<<<(NG * KXH + 255) / 256, 256>>>(Wih, Whh, Wd, Wfb);
    mean_h0c0_kernel<<<BB, 256>>>(enc, Wh0, bh0, Wc0, bc0);
    att1_kernel<<<dim3((BB * PP) / 64, AA / 128), 256>>>(enc, We, be);

    for (int t = 0; t < TT; t++) {
        att2_tf32_kernel<<<dim3(512 / 64, NS_ATT), 256>>>(t);
        attn_kernel<<<BB, 512>>>(enc, bd, bfb, wf, bf, lengths, captions,
                                 embW, out_alpha, t);
        gates_tf32_kernel<<<dim3(NG / 64, NS_G), 256>>>(t);
        lstm_kernel<<<BB, 512>>>(bih, bhh, lengths, t);
        pred_tf32_kernel<<<PRED_GRID, 256>>>(Wfc, bfc, lengths, out_pred, t);
    }
}

// round 8
// speedup vs baseline: 4.9813x; 1.0096x over previous
#include <cuda_runtime.h>
#include <math.h>
#include <stdint.h>

// Problem dims
#define BB 128
#define PP 196
#define EE 256
#define AA 256
#define DD 512
#define MME 512
#define VV 10000
#define LL 26
#define TT 25
#define KXH 1280     // emb(512) | ctx(256) | h(512)
#define NG  2048     // 4*DD gates
#define NS_ATT 16    // split-K for att2
#define NS_G   5     // split-K for gates
#define PRED_BN 64
#define PRED_GRID 157   // ceil(10000/64)

// -------------------- scratch --------------------------------------------
__device__ float g_att1[(size_t)BB * PP * AA];        // 25.7 MB
__device__ float g_c[BB * DD];
__device__ float g_xh[BB * KXH];                      // [emb | gated ctx | h]
__device__ float g_W[(size_t)NG * KXH];               // [Wih | Whh]
__device__ float g_Wdg[512 * 512];                    // [Wd ; Wfb]
__device__ float g_attp[NS_ATT * BB * 512];           // split-K partials (att2|gate)
__device__ float g_gatesp[NS_G * (size_t)BB * NG];    // split-K partials gates

// ---- 64(M)x128(N) fp32 SGEMM core (setup kernels only) ------------------
__device__ __forceinline__ void gemm64x128(
    const float* __restrict__ Amat, int lda,
    const float* __restrict__ Wmat, int ldw,
    int m0, int n0, int N, int kBeg, int kEnd,
    float acc[4][8])
{
    __shared__ float As[2][16][68];
    __shared__ float Bs[2][16][132];
    const int tid = threadIdx.x;
    const int ar  = tid >> 2;
    const int ak  = (tid & 3) << 2;
    const int tx  = tid & 15;
    const int ty  = tid >> 4;
    const bool okB0 = (n0 + ar)      < N;
    const bool okB1 = (n0 + ar + 64) < N;
    const float* Arow  = Amat + (size_t)(m0 + ar) * lda + ak;
    const float* Wrow0 = Wmat + (size_t)(n0 + ar) * ldw + ak;
    const float* Wrow1 = Wmat + (size_t)(n0 + ar + 64) * ldw + ak;
    const float4 f40 = make_float4(0.f, 0.f, 0.f, 0.f);

    float4 va  = *(const float4*)(Arow + kBeg);
    float4 vb0 = okB0 ? *(const float4*)(Wrow0 + kBeg) : f40;
    float4 vb1 = okB1 ? *(const float4*)(Wrow1 + kBeg) : f40;
    int buf = 0;
    As[0][ak+0][ar] = va.x;  As[0][ak+1][ar] = va.y;
    As[0][ak+2][ar] = va.z;  As[0][ak+3][ar] = va.w;
    Bs[0][ak+0][ar] = vb0.x; Bs[0][ak+1][ar] = vb0.y;
    Bs[0][ak+2][ar] = vb0.z; Bs[0][ak+3][ar] = vb0.w;
    Bs[0][ak+0][ar+64] = vb1.x; Bs[0][ak+1][ar+64] = vb1.y;
    Bs[0][ak+2][ar+64] = vb1.z; Bs[0][ak+3][ar+64] = vb1.w;
    __syncthreads();

    for (int k0 = kBeg; k0 < kEnd; k0 += 16) {
        const bool more = (k0 + 16) < kEnd;
        float4 na = f40, nb0 = f40, nb1 = f40;
        if (more) {
            na  = *(const float4*)(Arow + k0 + 16);
            if (okB0) nb0 = *(const float4*)(Wrow0 + k0 + 16);
            if (okB1) nb1 = *(const float4*)(Wrow1 + k0 + 16);
        }
        #pragma unroll
        for (int kk = 0; kk < 16; kk++) {
            float a[4], b[8];
            *(float4*)(a)     = *(const float4*)&As[buf][kk][ty << 2];
            *(float4*)(b)     = *(const float4*)&Bs[buf][kk][tx << 3];
            *(float4*)(b + 4) = *(const float4*)&Bs[buf][kk][(tx << 3) + 4];
            #pragma unroll
            for (int i = 0; i < 4; i++)
                #pragma unroll
                for (int j = 0; j < 8; j++)
                    acc[i][j] = fmaf(a[i], b[j], acc[i][j]);
        }
        if (more) {
            buf ^= 1;
            As[buf][ak+0][ar] = na.x;  As[buf][ak+1][ar] = na.y;
            As[buf][ak+2][ar] = na.z;  As[buf][ak+3][ar] = na.w;
            Bs[buf][ak+0][ar] = nb0.x; Bs[buf][ak+1][ar] = nb0.y;
            Bs[buf][ak+2][ar] = nb0.z; Bs[buf][ak+3][ar] = nb0.w;
            Bs[buf][ak+0][ar+64] = nb1.x; Bs[buf][ak+1][ar+64] = nb1.y;
            Bs[buf][ak+2][ar+64] = nb1.z; Bs[buf][ak+3][ar+64] = nb1.w;
            __syncthreads();
        }
    }
}

#define ZERO_ACC4(acc) \
    { _Pragma("unroll") for (int i = 0; i < 4; i++) \
      _Pragma("unroll") for (int j = 0; j < 8; j++) acc[i][j] = 0.f; }

__device__ __forceinline__ uint32_t f2tf32(float v) {
    uint32_t r;
    asm("cvt.rna.tf32.f32 %0, %1;" : "=r"(r) : "f"(v));
    return r;
}

__device__ __forceinline__ void mma_tf32(float c[4], const uint32_t a[4],
                                         const uint32_t b[2]) {
    asm volatile(
        "mma.sync.aligned.m16n8k8.row.col.f32.tf32.tf32.f32 "
        "{%0,%1,%2,%3}, {%4,%5,%6,%7}, {%8,%9}, {%0,%1,%2,%3};"
        : "+f"(c[0]), "+f"(c[1]), "+f"(c[2]), "+f"(c[3])
        : "r"(a[0]), "r"(a[1]), "r"(a[2]), "r"(a[3]), "r"(b[0]), "r"(b[1]));
}

// ---- 128(M) x 64(N) tf32x3 GEMM body: near-fp32 precision ----------------
// acc += A[0:128, kBeg:kEnd] @ W[n0:n0+64, kBeg:kEnd]^T  (256 threads)
// Warp w: M base (w&3)*32, N base (w>>2)*32; frag layout as pred kernel.
__device__ __forceinline__ void gemm_tf32x3(
    const float* __restrict__ A, int lda,
    const float* __restrict__ W, int ldw,
    int n0, int kBeg, int kEnd,
    float acc[2][4][4])
{
    __shared__ float As[128][36];
    __shared__ float Bs[64][36];
    const int tid = threadIdx.x;
    const int wid = tid >> 5, lane = tid & 31;
    const int gr = lane >> 2, ct = lane & 3;
    const int wm = (wid & 3) * 32;
    const int wn = (wid >> 2) * 32;

    for (int kb = kBeg; kb < kEnd; kb += 32) {
        __syncthreads();
        #pragma unroll
        for (int i = 0; i < 4; i++) {
            const int idx = tid + i * 256;
            const int r = idx >> 3, c = (idx & 7) << 2;
            float4 v = *(const float4*)(A + (size_t)r * lda + kb + c);
            As[r][c+0] = v.x; As[r][c+1] = v.y; As[r][c+2] = v.z; As[r][c+3] = v.w;
        }
        #pragma unroll
        for (int i = 0; i < 2; i++) {
            const int idx = tid + i * 256;
            const int r = idx >> 3, c = (idx & 7) << 2;
            float4 v = *(const float4*)(W + (size_t)(n0 + r) * ldw + kb + c);
            Bs[r][c+0] = v.x; Bs[r][c+1] = v.y; Bs[r][c+2] = v.z; Bs[r][c+3] = v.w;
        }
        __syncthreads();
        #pragma unroll
        for (int ks = 0; ks < 32; ks += 8) {
            uint32_t ah[2][4], al[2][4], bh[4][2], bl[4][2];
            #pragma unroll
            for (int mt = 0; mt < 2; mt++) {
                const int row = wm + mt * 16 + gr;
                float f0 = As[row][ks+ct],     f1 = As[row+8][ks+ct];
                float f2 = As[row][ks+ct+4],   f3 = As[row+8][ks+ct+4];
                ah[mt][0] = f2tf32(f0); al[mt][0] = f2tf32(f0 - __uint_as_float(ah[mt][0]));
                ah[mt][1] = f2tf32(f1); al[mt][1] = f2tf32(f1 - __uint_as_float(ah[mt][1]));
                ah[mt][2] = f2tf32(f2); al[mt][2] = f2tf32(f2 - __uint_as_float(ah[mt][2]));
                ah[mt][3] = f2tf32(f3); al[mt][3] = f2tf32(f3 - __uint_as_float(ah[mt][3]));
            }
            #pragma unroll
            for (int nt = 0; nt < 4; nt++) {
                const int rn = wn + nt * 8 + gr;
                float f0 = Bs[rn][ks+ct], f1 = Bs[rn][ks+ct+4];
                bh[nt][0] = f2tf32(f0); bl[nt][0] = f2tf32(f0 - __uint_as_float(bh[nt][0]));
                bh[nt][1] = f2tf32(f1); bl[nt][1] = f2tf32(f1 - __uint_as_float(bh[nt][1]));
            }
            #pragma unroll
            for (int mt = 0; mt < 2; mt++)
                #pragma unroll
                for (int nt = 0; nt < 4; nt++) {
                    mma_tf32(acc[mt][nt], ah[mt], bh[nt]);
                    mma_tf32(acc[mt][nt], ah[mt], bl[nt]);
                    mma_tf32(acc[mt][nt], al[mt], bh[nt]);
                }
        }
    }
}

#define ZERO_ACC244(acc) \
    { _Pragma("unroll") for (int mt = 0; mt < 2; mt++) \
      _Pragma("unroll") for (int nt = 0; nt < 4; nt++) \
      _Pragma("unroll") for (int r = 0; r < 4; r++) acc[mt][nt][r] = 0.f; }

// -------------------- setup: concat weights ------------------------------
__global__ __launch_bounds__(256) void concat_kernel(
    const float* __restrict__ Wih, const float* __restrict__ Whh,
    const float* __restrict__ Wd,  const float* __restrict__ Wfb)
{
    const int idx = blockIdx.x * 256 + threadIdx.x;
    if (idx < NG * KXH) {
        const int r = idx / KXH, c = idx - r * KXH;
        g_W[idx] = (c < 768) ? Wih[r * 768 + c] : Whh[r * 512 + (c - 768)];
    }
    if (idx < 512 * 512) {
        const int r = idx >> 9, c = idx & 511;
        g_Wdg[idx] = (r < 256) ? Wd[r * 512 + c] : Wfb[(r - 256) * 512 + c];
    }
}

// -------------------- setup: mean, h0, c0 --------------------------------
__global__ __launch_bounds__(256) void mean_h0c0_kernel(
    const float* __restrict__ enc,
    const float* __restrict__ Wh0, const float* __restrict__ bh0,
    const float* __restrict__ Wc0, const float* __restrict__ bc0)
{
    __shared__ float ms[EE];
    const int b = blockIdx.x, tid = threadIdx.x;
    float acc = 0.f;
    const float* eb = enc + (size_t)b * PP * EE + tid;
    #pragma unroll 4
    for (int p = 0; p < PP; p++) acc += eb[(size_t)p * EE];
    ms[tid] = acc * (1.0f / PP);
    __syncthreads();
    for (int j = tid; j < DD; j += 256) {
        float h = bh0[j], c = bc0[j];
        const float* wh = Wh0 + (size_t)j * EE;
        const float* wc = Wc0 + (size_t)j * EE;
        #pragma unroll 4
        for (int k = 0; k < EE; k++) { h = fmaf(ms[k], wh[k], h); c = fmaf(ms[k], wc[k], c); }
        g_xh[b * KXH + 768 + j] = h;
        g_c[b * DD + j] = c;
    }
}

// -------------------- setup: att1 = enc @ We^T + be ----------------------
__global__ __launch_bounds__(256) void att1_kernel(
    const float* __restrict__ enc,
    const float* __restrict__ We, const float* __restrict__ be)
{
    float acc[4][8]; ZERO_ACC4(acc);
    const int m0 = blockIdx.x * 64, n0 = blockIdx.y * 128;
    gemm64x128(enc, EE, We, EE, m0, n0, AA, 0, EE, acc);
    const int tx = threadIdx.x & 15, ty = threadIdx.x >> 4;
    #pragma unroll
    for (int i = 0; i < 4; i++) {
        const int m = m0 + (ty << 2) + i;
        #pragma unroll
        for (int j = 0; j < 8; j++) {
            const int n = n0 + (tx << 3) + j;
            g_att1[(size_t)m * AA + n] = acc[i][j] + be[n];
        }
    }
}

// ---------- per-step: att2|gate GEMM (tf32x3, split-K=16) ----------------
// C[128,512] = H[128,512] @ Wdg[512,512]^T ; block: n0 = bx*64, k = by*32
__global__ __launch_bounds__(256) void att2_tf32_kernel(int t)
{
    float acc[2][4][4]; ZERO_ACC244(acc);
    const int n0 = blockIdx.x * 64;
    const int s  = blockIdx.y;
    gemm_tf32x3(g_xh + 768, KXH, g_Wdg, 512, n0, s * 32, s * 32 + 32, acc);
    float* C = g_attp + s * (BB * 512);
    const int tid = threadIdx.x, wid = tid >> 5, lane = tid & 31;
    const int gr = lane >> 2, ct = lane & 3;
    const int wm = (wid & 3) * 32, wn = (wid >> 2) * 32;
    #pragma unroll
    for (int mt = 0; mt < 2; mt++) {
        const int r0 = wm + mt * 16 + gr, r1 = r0 + 8;
        #pragma unroll
        for (int nt = 0; nt < 4; nt++) {
            const int col = n0 + wn + nt * 8 + 2 * ct;
            C[(size_t)r0 * 512 + col]     = acc[mt][nt][0];
            C[(size_t)r0 * 512 + col + 1] = acc[mt][nt][1];
            C[(size_t)r1 * 512 + col]     = acc[mt][nt][2];
            C[(size_t)r1 * 512 + col + 1] = acc[mt][nt][3];
        }
    }
}

// ---------- per-step: fused gates GEMM (tf32x3, split-K=5) ---------------
// C[128,2048] = XH[128,1280] @ W[2048,1280]^T ; n0 = bx*64, k = by*256
__global__ __launch_bounds__(256) void gates_tf32_kernel(int t)
{
    float acc[2][4][4]; ZERO_ACC244(acc);
    const int n0 = blockIdx.x * 64;
    const int s  = blockIdx.y;
    gemm_tf32x3(g_xh, KXH, g_W, KXH, n0, s * 256, s * 256 + 256, acc);
    float* C = g_gatesp + (size_t)s * (BB * NG);
    const int tid = threadIdx.x, wid = tid >> 5, lane = tid & 31;
    const int gr = lane >> 2, ct = lane & 3;
    const int wm = (wid & 3) * 32, wn = (wid >> 2) * 32;
    #pragma unroll
    for (int mt = 0; mt < 2; mt++) {
        const int r0 = wm + mt * 16 + gr, r1 = r0 + 8;
        #pragma unroll
        for (int nt = 0; nt < 4; nt++) {
            const int col = n0 + wn + nt * 8 + 2 * ct;
            C[(size_t)r0 * NG + col]     = acc[mt][nt][0];
            C[(size_t)r0 * NG + col + 1] = acc[mt][nt][1];
            C[(size_t)r1 * NG + col]     = acc[mt][nt][2];
            C[(size_t)r1 * NG + col + 1] = acc[mt][nt][3];
        }
    }
}

// -------------------- per-step: attention fused --------------------------
__global__ __launch_bounds__(512) void attn_kernel(
    const float* __restrict__ enc,
    const float* __restrict__ bd, const float* __restrict__ bfb,
    const float* __restrict__ wf, const float* __restrict__ bfp,
    const int* __restrict__ lengths, const int* __restrict__ captions,
    const float* __restrict__ embW, float* __restrict__ out_alpha, int t)
{
    __shared__ float att2_s[AA];
    __shared__ float wf_s[AA];
    __shared__ float gate_s[EE];
    __shared__ float alpha_s[256];
    __shared__ float red[16];
    __shared__ float ctxp[2][EE];
    const int b = blockIdx.x, tid = threadIdx.x;
    float* arow = out_alpha + ((size_t)b * TT + t) * PP;
    if (t >= lengths[b] - 1) {
        if (tid < PP) arow[tid] = 0.f;
        return;
    }
    if (tid < 256) {
        float a2 = bd[tid];
        #pragma unroll
        for (int s = 0; s < NS_ATT; s++) a2 += g_attp[s * (BB * 512) + b * 512 + tid];
        att2_s[tid] = a2;
        wf_s[tid] = wf[tid];
    } else {
        const int j = tid - 256;
        float gv = bfb[j];
        #pragma unroll
        for (int s = 0; s < NS_ATT; s++) gv += g_attp[s * (BB * 512) + b * 512 + 256 + j];
        gate_s[j] = 1.f / (1.f + expf(-gv));
    }
    __syncthreads();
    const float bfv = bfp[0];
    const int warp = tid >> 5, lane = tid & 31;
    {
        const float* base = g_att1 + (size_t)b * PP * AA + lane * 8;
        int p = warp;
        float4 v0 = make_float4(0,0,0,0), v1 = make_float4(0,0,0,0);
        if (p < PP) {
            v0 = *(const float4*)(base + (size_t)p * AA);
            v1 = *(const float4*)(base + (size_t)p * AA + 4);
        }
        for (; p < PP; p += 16) {
            const int pn = p + 16;
            float4 n0v = make_float4(0,0,0,0), n1v = make_float4(0,0,0,0);
            if (pn < PP) {
                n0v = *(const float4*)(base + (size_t)pn * AA);
                n1v = *(const float4*)(base + (size_t)pn * AA + 4);
            }
            const int a0 = lane * 8;
            float s = 0.f;
            s += fmaxf(v0.x + att2_s[a0 + 0], 0.f) * wf_s[a0 + 0];
            s += fmaxf(v0.y + att2_s[a0 + 1], 0.f) * wf_s[a0 + 1];
            s += fmaxf(v0.z + att2_s[a0 + 2], 0.f) * wf_s[a0 + 2];
            s += fmaxf(v0.w + att2_s[a0 + 3], 0.f) * wf_s[a0 + 3];
            s += fmaxf(v1.x + att2_s[a0 + 4], 0.f) * wf_s[a0 + 4];
            s += fmaxf(v1.y + att2_s[a0 + 5], 0.f) * wf_s[a0 + 5];
            s += fmaxf(v1.z + att2_s[a0 + 6], 0.f) * wf_s[a0 + 6];
            s += fmaxf(v1.w + att2_s[a0 + 7], 0.f) * wf_s[a0 + 7];
            #pragma unroll
            for (int off = 16; off; off >>= 1) s += __shfl_down_sync(0xffffffffu, s, off);
            if (lane == 0) alpha_s[p] = s + bfv;
            v0 = n0v; v1 = n1v;
        }
    }
    __syncthreads();
    const float sc = (tid < PP) ? alpha_s[tid] : -3.4e38f;
    float m = sc;
    #pragma unroll
    for (int off = 16; off; off >>= 1) m = fmaxf(m, __shfl_down_sync(0xffffffffu, m, off));
    if (lane == 0) red[warp] = m;
    __syncthreads();
    if (tid == 0) {
        float mm = red[0];
        #pragma unroll
        for (int i = 1; i < 16; i++) mm = fmaxf(mm, red[i]);
        red[0] = mm;
    }
    __syncthreads();
    const float mx = red[0];
    __syncthreads();
    const float ev = (tid < PP) ? expf(sc - mx) : 0.f;
    float sum = ev;
    #pragma unroll
    for (int off = 16; off; off >>= 1) sum += __shfl_down_sync(0xffffffffu, sum, off);
    if (lane == 0) red[warp] = sum;
    __syncthreads();
    if (tid == 0) {
        float ss = 0.f;
        #pragma unroll
        for (int i = 0; i < 16; i++) ss += red[i];
        red[0] = 1.f / ss;
    }
    __syncthreads();
    const float inv = red[0];
    if (tid < PP) {
        const float al = ev * inv;
        alpha_s[tid] = al;
        arow[tid] = al;
    }
    __syncthreads();
    {
        const int e = tid & 255, half = tid >> 8;
        const int pB = half * 98, pE = pB + 98;
        float acc = 0.f;
        const float* eb = enc + (size_t)b * PP * EE + e;
        #pragma unroll 8
        for (int p = pB; p < pE; p++) acc = fmaf(eb[(size_t)p * EE], alpha_s[p], acc);
        ctxp[half][e] = acc;
    }
    __syncthreads();
    if (tid < 256)
        g_xh[b * KXH + 512 + tid] = (ctxp[0][tid] + ctxp[1][tid]) * gate_s[tid];
    {
        const int cap = captions[b * LL + t];
        g_xh[b * KXH + tid] = embW[(size_t)cap * MME + tid];
    }
}

// -------------------- per-step: LSTM pointwise (reduce + act) ------------
__global__ __launch_bounds__(512) void lstm_kernel(
    const float* __restrict__ bih, const float* __restrict__ bhh,
    const int* __restrict__ lengths, int t)
{
    const int b = blockIdx.x, d = threadIdx.x;
    if (t >= lengths[b] - 1) return;
    float v[4];
    #pragma unroll
    for (int g = 0; g < 4; g++) {
        const int n = g * DD + d;
        float x = bih[n] + bhh[n];
        #pragma unroll
        for (int s = 0; s < NS_G; s++)
            x += g_gatesp[(size_t)s * (BB * NG) + (size_t)b * NG + n];
        v[g] = x;
    }
    const float c  = g_c[b * DD + d];
    const float si = 1.f / (1.f + expf(-v[0]));
    const float sf = 1.f / (1.f + expf(-v[1]));
    const float so = 1.f / (1.f + expf(-v[3]));
    const float cn = sf * c + si * tanhf(v[2]);
    const float hn = so * tanhf(cn);
    g_c[b * DD + d] = cn;
    g_xh[b * KXH + 768 + d] = hn;
}

// -------------------- per-step: vocab projection (tf32 tensor cores) -----
__global__ __launch_bounds__(256) void pred_tf32_kernel(
    const float* __restrict__ Wfc, const float* __restrict__ bfc,
    const int* __restrict__ lengths, float* __restrict__ out, int t)
{
    __shared__ uint32_t As[128][36];
    __shared__ uint32_t Bs[64][36];
    __shared__ int len_s[BB];
    const int tid  = threadIdx.x;
    const int wid  = tid >> 5, lane = tid & 31;
    const int gr   = lane >> 2, ct = lane & 3;
    const int wm   = (wid & 3) * 32;
    const int wn   = (wid >> 2) * 32;
    const int n0   = blockIdx.x * PRED_BN;
    const float* H = g_xh + 768;

    if (tid < BB) len_s[tid] = lengths[tid];

    float acc[2][4][4];
    #pragma unroll
    for (int mt = 0; mt < 2; mt++)
        #pragma unroll
        for (int nt = 0; nt < 4; nt++)
            #pragma unroll
            for (int r = 0; r < 4; r++) acc[mt][nt][r] = 0.f;

    for (int kb = 0; kb < DD; kb += 32) {
        __syncthreads();
        #pragma unroll
        for (int i = 0; i < 4; i++) {
            const int idx = tid + i * 256;
            const int r = idx >> 3, c = (idx & 7) << 2;
            float4 v = *(const float4*)(H + (size_t)r * KXH + kb + c);
            As[r][c + 0] = f2tf32(v.x); As[r][c + 1] = f2tf32(v.y);
            As[r][c + 2] = f2tf32(v.z); As[r][c + 3] = f2tf32(v.w);
        }
        #pragma unroll
        for (int i = 0; i < 2; i++) {
            const int idx = tid + i * 256;
            const int r = idx >> 3, c = (idx & 7) << 2;
            const int n = n0 + r;
            float4 v = (n < VV) ? *(const float4*)(Wfc + (size_t)n * DD + kb + c)
                                : make_float4(0.f, 0.f, 0.f, 0.f);
            Bs[r][c + 0] = f2tf32(v.x); Bs[r][c + 1] = f2tf32(v.y);
            Bs[r][c + 2] = f2tf32(v.z); Bs[r][c + 3] = f2tf32(v.w);
        }
        __syncthreads();
        #pragma unroll
        for (int ks = 0; ks < 32; ks += 8) {
            uint32_t a[2][4], b[4][2];
            #pragma unroll
            for (int mt = 0; mt < 2; mt++) {
                const int row = wm + mt * 16 + gr;
                a[mt][0] = As[row][ks + ct];
                a[mt][1] = As[row + 8][ks + ct];
                a[mt][2] = As[row][ks + ct + 4];
                a[mt][3] = As[row + 8][ks + ct + 4];
            }
            #pragma unroll
            for (int nt = 0; nt < 4; nt++) {
                const int rn = wn + nt * 8 + gr;
                b[nt][0] = Bs[rn][ks + ct];
                b[nt][1] = Bs[rn][ks + ct + 4];
            }
            #pragma unroll
            for (int mt = 0; mt < 2; mt++)
                #pragma unroll
                for (int nt = 0; nt < 4; nt++)
                    mma_tf32(acc[mt][nt], a[mt], b[nt]);
        }
    }

    #pragma unroll
    for (int mt = 0; mt < 2; mt++) {
        const int r0 = wm + mt * 16 + gr;
        const int r1 = r0 + 8;
        const bool act0 = t < len_s[r0] - 1;
        const bool act1 = t < len_s[r1] - 1;
        #pragma unroll
        for (int nt = 0; nt < 4; nt++) {
            const int col = n0 + wn + nt * 8 + 2 * ct;
            if (col < VV) {
                const float bz0 = bfc[col];
                out[((size_t)r0 * TT + t) * VV + col] = act0 ? (acc[mt][nt][0] + bz0) : 0.f;
                out[((size_t)r1 * TT + t) * VV + col] = act1 ? (acc[mt][nt][2] + bz0) : 0.f;
            }
            if (col + 1 < VV) {
                const float bz1 = bfc[col + 1];
                out[((size_t)r0 * TT + t) * VV + col + 1] = act0 ? (acc[mt][nt][1] + bz1) : 0.f;
                out[((size_t)r1 * TT + t) * VV + col + 1] = act1 ? (acc[mt][nt][3] + bz1) : 0.f;
            }
        }
    }
}

// -------------------- launch -------------------------------------------
extern "C" void kernel_launch(void* const* d_in, const int* in_sizes, int n_in,
                              void* d_out, int out_size) {
    const float* enc      = (const float*)d_in[0];
    const int*   captions = (const int*)  d_in[1];
    const int*   lengths  = (const int*)  d_in[2];
    const float* embW     = (const float*)d_in[3];
    const float* We       = (const float*)d_in[4];
    const float* be       = (const float*)d_in[5];
    const float* Wd       = (const float*)d_in[6];
    const float* bd       = (const float*)d_in[7];
    const float* wf       = (const float*)d_in[8];
    const float* bf       = (const float*)d_in[9];
    const float* Wih      = (const float*)d_in[10];
    const float* bih      = (const float*)d_in[11];
    const float* Whh      = (const float*)d_in[12];
    const float* bhh      = (const float*)d_in[13];
    const float* Wh0      = (const float*)d_in[14];
    const float* bh0      = (const float*)d_in[15];
    const float* Wc0      = (const float*)d_in[16];
    const float* bc0      = (const float*)d_in[17];
    const float* Wfb      = (const float*)d_in[18];
    const float* bfb      = (const float*)d_in[19];
    const float* Wfc      = (const float*)d_in[20];
    const float* bfc      = (const float*)d_in[21];

    float* out_pred  = (float*)d_out;
    float* out_alpha = out_pred + (size_t)BB * TT * VV;

    concat_kernel<<<(NG * KXH + 255) / 256, 256>>>(Wih, Whh, Wd, Wfb);
    mean_h0c0_kernel<<<BB, 256>>>(enc, Wh0, bh0, Wc0, bc0);
    att1_kernel<<<dim3((BB * PP) / 64, AA / 128), 256>>>(enc, We, be);

    for (int t = 0; t < TT; t++) {
        att2_tf32_kernel<<<dim3(512 / 64, NS_ATT), 256>>>(t);
        attn_kernel<<<BB, 512>>>(enc, bd, bfb, wf, bf, lengths, captions,
                                 embW, out_alpha, t);
        gates_tf32_kernel<<<dim3(NG / 64, NS_G), 256>>>(t);
        lstm_kernel<<<BB, 512>>>(bih, bhh, lengths, t);
        pred_tf32_kernel<<<PRED_GRID, 256>>>(Wfc, bfc, lengths, out_pred, t);
    }
}